// round 1
// baseline (speedup 1.0000x reference)
#include <cuda_runtime.h>

#define E_MAX 100000
#define M_MAX 300000
#define G_MAX 256

// ---------------- scratch (device globals; no allocations allowed) ----------
__device__ float g_LS[E_MAX * 64];     // link state, ld=64
__device__ float g_NS[E_MAX * 64];     // node state (59 used), ld=64
__device__ float g_PQ[E_MAX * 128];    // P | Q per state, ld=128
__device__ float g_agg[E_MAX * 64];    // aggregated messages, ld=64
__device__ float g_xm[E_MAX * 192];    // GRU x-gates, ld=192
__device__ float g_hm[E_MAX * 192];    // GRU h-gates, ld=192
__device__ int   g_cnt[E_MAX];
__device__ int   g_rowptr[E_MAX];
__device__ int   g_cursor[E_MAX];
__device__ int   g_csrf[M_MAX];        // states_first grouped by states_second
__device__ int   g_bsums[256];
__device__ float g_pool[G_MAX * 123];
__device__ float g_h1[G_MAX * 256];
__device__ float g_h2[G_MAX * 256];

// ---------------- helpers ---------------------------------------------------
__device__ __forceinline__ float seluf(float x) {
    const float sc = 1.0507009873554805f, al = 1.6732632423543772f;
    return x > 0.f ? sc * x : sc * al * (__expf(x) - 1.f);
}
__device__ __forceinline__ float sigm(float x) { return 1.f / (1.f + __expf(-x)); }

// ---------------- init / CSR build ------------------------------------------
__global__ void k_copy_f(float* dst, const float* src, int n) {
    int i = blockIdx.x * blockDim.x + threadIdx.x;
    if (i < n) dst[i] = src[i];
}
__global__ void k_copy_ns(const float* src, int E) {
    int i = blockIdx.x * blockDim.x + threadIdx.x;
    if (i < E * 59) {
        int e = i / 59, c = i % 59;
        g_NS[e * 64 + c] = src[i];
    }
}
__global__ void k_zero_i(int* p, int n) {
    int i = blockIdx.x * blockDim.x + threadIdx.x;
    if (i < n) p[i] = 0;
}
__global__ void k_zero_f(float* p, int n) {
    int i = blockIdx.x * blockDim.x + threadIdx.x;
    if (i < n) p[i] = 0.f;
}
__global__ void k_hist(const int* __restrict__ second, int M) {
    int j = blockIdx.x * blockDim.x + threadIdx.x;
    if (j < M) atomicAdd(&g_cnt[second[j]], 1);
}
__global__ void k_scan1(int E) {
    __shared__ int s[1024];
    int i = blockIdx.x * 1024 + threadIdx.x;
    int v = (i < E) ? g_cnt[i] : 0;
    s[threadIdx.x] = v;
    __syncthreads();
    for (int o = 1; o < 1024; o <<= 1) {
        int t = (threadIdx.x >= o) ? s[threadIdx.x - o] : 0;
        __syncthreads();
        s[threadIdx.x] += t;
        __syncthreads();
    }
    if (i < E) g_rowptr[i] = s[threadIdx.x];  // inclusive within block
    if (threadIdx.x == 1023) g_bsums[blockIdx.x] = s[1023];
}
__global__ void k_scan2(int nb) {
    if (threadIdx.x == 0 && blockIdx.x == 0) {
        int run = 0;
        for (int b = 0; b < nb; b++) { int t = g_bsums[b]; g_bsums[b] = run; run += t; }
    }
}
__global__ void k_scan3(int E) {
    int i = blockIdx.x * blockDim.x + threadIdx.x;
    if (i < E) {
        int ex = g_rowptr[i] - g_cnt[i] + g_bsums[i / 1024];
        g_rowptr[i] = ex;
        g_cursor[i] = ex;
    }
}
__global__ void k_fill(const int* __restrict__ first, const int* __restrict__ second, int M) {
    int j = blockIdx.x * blockDim.x + threadIdx.x;
    if (j < M) {
        int pos = atomicAdd(&g_cursor[second[j]], 1);
        g_csrf[pos] = first[j];
    }
}

// ---------------- tiled fp32 GEMM: C[rows,N] = A[rows,K] @ W + bias ----------
// W columns [0,n0) come from W0 (row stride n0); columns [n0,N) from W1
// (row stride N-n0). 64x64 tile, 256 threads, 4x4 microtile, K <= 64.
__global__ void k_gemm(const float* __restrict__ A, int lda, int rows,
                       const float* __restrict__ W0, int n0,
                       const float* __restrict__ W1,
                       const float* __restrict__ bias,
                       int K, int N, float* __restrict__ C, int ldc) {
    __shared__ float As[64 * 68];
    __shared__ float Ws[64 * 64];
    const int row0 = blockIdx.x * 64, col0 = blockIdx.y * 64;
    const int tid = threadIdx.x;
    const int n1 = N - n0;

    for (int idx = tid; idx < 64 * K; idx += 256) {
        int m = idx / K, k = idx % K;
        int r = row0 + m;
        As[m * 68 + k] = (r < rows) ? A[r * lda + k] : 0.f;
    }
    for (int idx = tid; idx < K * 64; idx += 256) {
        int k = idx / 64, c = idx % 64;
        int gc = col0 + c;
        float w = 0.f;
        if (gc < N) w = (gc < n0) ? W0[k * n0 + gc] : W1[k * n1 + (gc - n0)];
        Ws[k * 64 + c] = w;
    }
    __syncthreads();

    const int tx = tid & 15, ty = tid >> 4;
    float acc[4][4] = {};
#pragma unroll 4
    for (int k = 0; k < K; k++) {
        float a[4];
#pragma unroll
        for (int i = 0; i < 4; i++) a[i] = As[(ty * 4 + i) * 68 + k];
        float4 b = *(const float4*)&Ws[k * 64 + tx * 4];
#pragma unroll
        for (int i = 0; i < 4; i++) {
            acc[i][0] += a[i] * b.x;
            acc[i][1] += a[i] * b.y;
            acc[i][2] += a[i] * b.z;
            acc[i][3] += a[i] * b.w;
        }
    }
#pragma unroll
    for (int i = 0; i < 4; i++) {
        int r = row0 + ty * 4 + i;
        if (r >= rows) continue;
#pragma unroll
        for (int j = 0; j < 4; j++) {
            int gc = col0 + tx * 4 + j;
            if (gc < N) {
                float v = acc[i][j];
                if (bias) v += bias[gc];
                C[r * ldc + gc] = v;
            }
        }
    }
}

// ---------------- message aggregation (CSR, warp per target) -----------------
// agg[e,c] = sum_{j: second[j]==e} selu(P[first[j],c] + Q[e,c] + bias[c])
__global__ void k_agg(int E, int D, int qOff, const float* __restrict__ bias) {
    int w = (blockIdx.x * blockDim.x + threadIdx.x) >> 5;
    if (w >= E) return;
    int lane = threadIdx.x & 31;
    int c0 = lane, c1 = lane + 32;
    bool v1 = (c1 < D);
    float q0 = g_PQ[w * 128 + qOff + c0] + bias[c0];
    float q1 = v1 ? (g_PQ[w * 128 + qOff + c1] + bias[c1]) : 0.f;
    float a0 = 0.f, a1 = 0.f;
    int s = g_rowptr[w], n = g_cnt[w];
    for (int i = 0; i < n; i++) {
        int f = g_csrf[s + i];
        const float* p = g_PQ + f * 128;
        a0 += seluf(p[c0] + q0);
        if (v1) a1 += seluf(p[c1] + q1);
    }
    g_agg[w * 64 + c0] = a0;
    if (v1) g_agg[w * 64 + c1] = a1;
}

// ---------------- GRU elementwise combine ------------------------------------
__global__ void k_gru(float* __restrict__ h, int E, int D) {
    int idx = blockIdx.x * blockDim.x + threadIdx.x;
    if (idx >= E * D) return;
    int e = idx / D, d = idx % D;
    const float* xm = g_xm + e * 192;
    const float* hm = g_hm + e * 192;
    float z = sigm(xm[d] + hm[d]);
    float r = sigm(xm[d + D] + hm[d + D]);
    float c = tanhf(xm[d + 2 * D] + r * hm[d + 2 * D]);
    float hv = h[e * 64 + d];
    h[e * 64 + d] = z * hv + (1.f - z) * c;
}

// ---------------- readout -----------------------------------------------------
__global__ void k_pool(const int* __restrict__ gid, int E) {
    int idx = blockIdx.x * blockDim.x + threadIdx.x;
    if (idx >= E * 123) return;
    int e = idx / 123, c = idx % 123;
    float v = (c < 64) ? g_LS[e * 64 + c] : g_NS[e * 64 + (c - 64)];
    atomicAdd(&g_pool[gid[e] * 123 + c], v);
}
__global__ void k_mlp(const float* __restrict__ in, int ldin, int K,
                      const float* __restrict__ W, const float* __restrict__ b,
                      int N, float* __restrict__ out, int ldout, int act) {
    __shared__ float s[256];
    int row = blockIdx.x;
    for (int k = threadIdx.x; k < K; k += blockDim.x) s[k] = in[row * ldin + k];
    __syncthreads();
    for (int t = threadIdx.x; t < N; t += blockDim.x) {
        float acc = b[t];
        for (int k = 0; k < K; k++) acc += s[k] * W[k * N + t];
        if (act) acc = seluf(acc);
        out[row * ldout + t] = acc;
    }
}

// ---------------- launch ------------------------------------------------------
extern "C" void kernel_launch(void* const* d_in, const int* in_sizes, int n_in,
                              void* d_out, int out_size) {
    int idx = 0;
    const float* graph_state = (const float*)d_in[idx++];
    const float* node_state  = (const float*)d_in[idx++];
    const int*   first       = (const int*)d_in[idx++];
    const int*   second      = (const int*)d_in[idx++];
    const int*   gids        = (const int*)d_in[idx++];
    // optional scalar states_num_edges occupying a slot
    if (idx < n_in && in_sizes[idx] == 1) idx++;
    const float* W_msg  = (const float*)d_in[idx++];
    const float* b_msg  = (const float*)d_in[idx++];
    const float* Wx_e   = (const float*)d_in[idx++];
    const float* Wh_e   = (const float*)d_in[idx++];
    const float* bx_e   = (const float*)d_in[idx++];
    const float* bh_e   = (const float*)d_in[idx++];
    const float* W_nmsg = (const float*)d_in[idx++];
    const float* b_nmsg = (const float*)d_in[idx++];
    const float* Wx_n   = (const float*)d_in[idx++];
    const float* Wh_n   = (const float*)d_in[idx++];
    const float* bx_n   = (const float*)d_in[idx++];
    const float* bh_n   = (const float*)d_in[idx++];
    const float* W1     = (const float*)d_in[idx++];
    const float* b1     = (const float*)d_in[idx++];
    const float* W2     = (const float*)d_in[idx++];
    const float* b2     = (const float*)d_in[idx++];
    const float* W3     = (const float*)d_in[idx++];
    const float* b3     = (const float*)d_in[idx++];

    const int E = in_sizes[0] / 64;
    const int M = in_sizes[3];
    const int G = out_size;

    float *LS, *NS, *PQ, *AG, *XM, *HM, *POOL, *H1, *H2;
    int *CNT;
    cudaGetSymbolAddress((void**)&LS, g_LS);
    cudaGetSymbolAddress((void**)&NS, g_NS);
    cudaGetSymbolAddress((void**)&PQ, g_PQ);
    cudaGetSymbolAddress((void**)&AG, g_agg);
    cudaGetSymbolAddress((void**)&XM, g_xm);
    cudaGetSymbolAddress((void**)&HM, g_hm);
    cudaGetSymbolAddress((void**)&POOL, g_pool);
    cudaGetSymbolAddress((void**)&H1, g_h1);
    cudaGetSymbolAddress((void**)&H2, g_h2);
    cudaGetSymbolAddress((void**)&CNT, g_cnt);

    const int T256 = 256;
    auto gs = [](int n, int b) { return (n + b - 1) / b; };

    // init states
    k_copy_f<<<gs(E * 64, T256), T256>>>(LS, graph_state, E * 64);
    k_copy_ns<<<gs(E * 59, T256), T256>>>(node_state, E);

    // CSR build (once; indices are iteration-invariant)
    k_zero_i<<<gs(E, T256), T256>>>(CNT, E);
    k_hist<<<gs(M, T256), T256>>>(second, M);
    int nb = gs(E, 1024);
    k_scan1<<<nb, 1024>>>(E);
    k_scan2<<<1, 32>>>(nb);
    k_scan3<<<gs(E, T256), T256>>>(E);
    k_fill<<<gs(M, T256), T256>>>(first, second, M);

    const int rowsB = gs(E, 64);
    // ---- edge message passing: T=4 ----
    for (int t = 0; t < 4; t++) {
        k_gemm<<<dim3(rowsB, 2), 256>>>(LS, 64, E, W_msg, 64, W_msg + 64 * 64,
                                        nullptr, 64, 128, PQ, 128);
        k_agg<<<gs(E * 32, 256), 256>>>(E, 64, 64, b_msg);
        k_gemm<<<dim3(rowsB, 3), 256>>>(AG, 64, E, Wx_e, 192, nullptr, bx_e,
                                        64, 192, XM, 192);
        k_gemm<<<dim3(rowsB, 3), 256>>>(LS, 64, E, Wh_e, 192, nullptr, bh_e,
                                        64, 192, HM, 192);
        k_gru<<<gs(E * 64, T256), T256>>>(LS, E, 64);
    }
    // ---- node message passing: T=4 ----
    for (int t = 0; t < 4; t++) {
        k_gemm<<<dim3(rowsB, 2), 256>>>(NS, 64, E, W_nmsg, 59, W_nmsg + 59 * 59,
                                        nullptr, 59, 118, PQ, 128);
        k_agg<<<gs(E * 32, 256), 256>>>(E, 59, 59, b_nmsg);
        k_gemm<<<dim3(rowsB, 3), 256>>>(AG, 64, E, Wx_n, 177, nullptr, bx_n,
                                        59, 177, XM, 192);
        k_gemm<<<dim3(rowsB, 3), 256>>>(NS, 64, E, Wh_n, 177, nullptr, bh_n,
                                        59, 177, HM, 192);
        k_gru<<<gs(E * 59, T256), T256>>>(NS, E, 59);
    }

    // ---- readout ----
    k_zero_f<<<gs(G * 123, T256), T256>>>(POOL, G * 123);
    k_pool<<<gs(E * 123, T256), T256>>>(gids, E);
    k_mlp<<<G, 256>>>(POOL, 123, 123, W1, b1, 256, H1, 256, 1);
    k_mlp<<<G, 256>>>(H1, 256, 256, W2, b2, 256, H2, 256, 1);
    k_mlp<<<G, 256>>>(H2, 256, 256, W3, b3, 1, (float*)d_out, 1, 0);
}

// round 2
// speedup vs baseline: 1.1509x; 1.1509x over previous
#include <cuda_runtime.h>

#define E_MAX 100000
#define M_MAX 300000
#define G_MAX 256

// ---------------- scratch (device globals; no allocations allowed) ----------
__device__ float g_LS[E_MAX * 64];     // link state, ld=64
__device__ float g_NS[E_MAX * 64];     // node state (59 used), ld=64
__device__ float g_PQ[E_MAX * 128];    // P | Q per state, ld=128
__device__ float g_agg[E_MAX * 64];    // aggregated messages, ld=64
__device__ int   g_cnt[E_MAX];
__device__ int   g_rowptr[E_MAX];
__device__ int   g_cursor[E_MAX];
__device__ int   g_csrf[M_MAX];        // states_first grouped by states_second
__device__ int   g_bsums[256];
// graph pooling CSR
__device__ int   g_gcnt[G_MAX];
__device__ int   g_grow[G_MAX];
__device__ int   g_gcur[G_MAX];
__device__ int   g_glist[E_MAX];
__device__ float g_pool[G_MAX * 123];
__device__ float g_h1[G_MAX * 256];
__device__ float g_h2[G_MAX * 256];

// ---------------- helpers ---------------------------------------------------
__device__ __forceinline__ float seluf(float x) {
    const float sc = 1.0507009873554805f, al = 1.6732632423543772f;
    return x > 0.f ? sc * x : sc * al * (__expf(x) - 1.f);
}
__device__ __forceinline__ float sigm(float x) { return 1.f / (1.f + __expf(-x)); }

// ---------------- init / CSR build ------------------------------------------
__global__ void k_copy_f(float* dst, const float* src, int n) {
    int i = blockIdx.x * blockDim.x + threadIdx.x;
    if (i < n) dst[i] = src[i];
}
__global__ void k_copy_ns(const float* src, int E) {
    int i = blockIdx.x * blockDim.x + threadIdx.x;
    if (i < E * 59) {
        int e = i / 59, c = i % 59;
        g_NS[e * 64 + c] = src[i];
    }
}
__global__ void k_zero_i(int* p, int n) {
    int i = blockIdx.x * blockDim.x + threadIdx.x;
    if (i < n) p[i] = 0;
}
__global__ void k_hist(const int* __restrict__ second, int M) {
    int j = blockIdx.x * blockDim.x + threadIdx.x;
    if (j < M) atomicAdd(&g_cnt[second[j]], 1);
}
__global__ void k_scan1(int E) {
    __shared__ int s[1024];
    int i = blockIdx.x * 1024 + threadIdx.x;
    int v = (i < E) ? g_cnt[i] : 0;
    s[threadIdx.x] = v;
    __syncthreads();
    for (int o = 1; o < 1024; o <<= 1) {
        int t = (threadIdx.x >= o) ? s[threadIdx.x - o] : 0;
        __syncthreads();
        s[threadIdx.x] += t;
        __syncthreads();
    }
    if (i < E) g_rowptr[i] = s[threadIdx.x];  // inclusive within block
    if (threadIdx.x == 1023) g_bsums[blockIdx.x] = s[1023];
}
__global__ void k_scan2(int nb) {
    if (threadIdx.x == 0 && blockIdx.x == 0) {
        int run = 0;
        for (int b = 0; b < nb; b++) { int t = g_bsums[b]; g_bsums[b] = run; run += t; }
    }
}
__global__ void k_scan3(int E) {
    int i = blockIdx.x * blockDim.x + threadIdx.x;
    if (i < E) {
        int ex = g_rowptr[i] - g_cnt[i] + g_bsums[i / 1024];
        g_rowptr[i] = ex;
        g_cursor[i] = ex;
    }
}
__global__ void k_fill(const int* __restrict__ first, const int* __restrict__ second, int M) {
    int j = blockIdx.x * blockDim.x + threadIdx.x;
    if (j < M) {
        int pos = atomicAdd(&g_cursor[second[j]], 1);
        g_csrf[pos] = first[j];
    }
}
// graph CSR
__global__ void k_ghist(const int* __restrict__ gid, int E) {
    int i = blockIdx.x * blockDim.x + threadIdx.x;
    if (i < E) atomicAdd(&g_gcnt[gid[i]], 1);
}
__global__ void k_gscan(int G) {
    __shared__ int s[G_MAX];
    int t = threadIdx.x;
    s[t] = (t < G) ? g_gcnt[t] : 0;
    __syncthreads();
    for (int o = 1; o < G_MAX; o <<= 1) {
        int v = (t >= o) ? s[t - o] : 0;
        __syncthreads();
        s[t] += v;
        __syncthreads();
    }
    if (t < G) {
        int ex = s[t] - g_gcnt[t];
        g_grow[t] = ex;
        g_gcur[t] = ex;
    }
}
__global__ void k_gfill(const int* __restrict__ gid, int E) {
    int i = blockIdx.x * blockDim.x + threadIdx.x;
    if (i < E) {
        int pos = atomicAdd(&g_gcur[gid[i]], 1);
        g_glist[pos] = i;
    }
}

// ---------------- tiled fp32 GEMM: C[rows,N] = A[rows,K] @ W ------------------
// W columns [0,n0) from W0 (row stride n0); columns [n0,N) from W1 (row stride N-n0).
__global__ void k_gemm(const float* __restrict__ A, int lda, int rows,
                       const float* __restrict__ W0, int n0,
                       const float* __restrict__ W1,
                       int K, int N, float* __restrict__ C, int ldc) {
    __shared__ float As[64 * 68];
    __shared__ float Ws[64 * 64];
    const int row0 = blockIdx.x * 64, col0 = blockIdx.y * 64;
    const int tid = threadIdx.x;
    const int n1 = N - n0;

    for (int idx = tid; idx < 64 * K; idx += 256) {
        int m = idx / K, k = idx % K;
        int r = row0 + m;
        As[m * 68 + k] = (r < rows) ? A[r * lda + k] : 0.f;
    }
    for (int idx = tid; idx < K * 64; idx += 256) {
        int k = idx / 64, c = idx % 64;
        int gc = col0 + c;
        float w = 0.f;
        if (gc < N) w = (gc < n0) ? W0[k * n0 + gc] : W1[k * n1 + (gc - n0)];
        Ws[k * 64 + c] = w;
    }
    __syncthreads();

    const int tx = tid & 15, ty = tid >> 4;
    float acc[4][4] = {};
#pragma unroll 8
    for (int k = 0; k < K; k++) {
        float a[4];
#pragma unroll
        for (int i = 0; i < 4; i++) a[i] = As[(ty * 4 + i) * 68 + k];
        float4 b = *(const float4*)&Ws[k * 64 + tx * 4];
#pragma unroll
        for (int i = 0; i < 4; i++) {
            acc[i][0] += a[i] * b.x;
            acc[i][1] += a[i] * b.y;
            acc[i][2] += a[i] * b.z;
            acc[i][3] += a[i] * b.w;
        }
    }
#pragma unroll
    for (int i = 0; i < 4; i++) {
        int r = row0 + ty * 4 + i;
        if (r >= rows) continue;
#pragma unroll
        for (int j = 0; j < 4; j++) {
            int gc = col0 + tx * 4 + j;
            if (gc < N) C[r * ldc + gc] = acc[i][j];
        }
    }
}

// ---------------- message aggregation (CSR, warp per target) -----------------
// agg[e,c] = sum_{j: second[j]==e} selu(P[first[j],c] + Q[e,c] + bias[c])
__global__ void k_agg(int E, int D, int qOff, const float* __restrict__ bias) {
    int w = (blockIdx.x * blockDim.x + threadIdx.x) >> 5;
    if (w >= E) return;
    int lane = threadIdx.x & 31;
    int c0 = lane, c1 = lane + 32;
    bool v1 = (c1 < D);
    float q0 = g_PQ[w * 128 + qOff + c0] + bias[c0];
    float q1 = v1 ? (g_PQ[w * 128 + qOff + c1] + bias[c1]) : 0.f;
    float a0 = 0.f, a1 = 0.f;
    int s = g_rowptr[w], n = g_cnt[w];
    int i = 0;
    for (; i + 2 <= n; i += 2) {
        int f0 = g_csrf[s + i], f1 = g_csrf[s + i + 1];
        const float* p0 = g_PQ + (size_t)f0 * 128;
        const float* p1 = g_PQ + (size_t)f1 * 128;
        float x00 = p0[c0], x10 = p1[c0];
        float x01 = v1 ? p0[c1] : 0.f, x11 = v1 ? p1[c1] : 0.f;
        a0 += seluf(x00 + q0) + seluf(x10 + q0);
        if (v1) a1 += seluf(x01 + q1) + seluf(x11 + q1);
    }
    for (; i < n; i++) {
        int f = g_csrf[s + i];
        const float* p = g_PQ + (size_t)f * 128;
        a0 += seluf(p[c0] + q0);
        if (v1) a1 += seluf(p[c1] + q1);
    }
    g_agg[w * 64 + c0] = a0;
    if (v1) g_agg[w * 64 + c1] = a1;
}

// ---------------- fused GRU: gates GEMMs + elementwise, no global temps ------
// h[row0..row0+63] = GRU(agg, h). D <= 64. Wx/Wh are [D, 3D], gate order z,r,hh.
#define PAD 65
__global__ void __launch_bounds__(256) k_gru_fused(
        float* __restrict__ H, const float* __restrict__ AG,
        const float* __restrict__ Wx, const float* __restrict__ Wh,
        const float* __restrict__ bx, const float* __restrict__ bh,
        int E, int D) {
    extern __shared__ float sm[];
    float* As = sm;                 // 64 x PAD
    float* Hs = sm + 64 * PAD;      // 64 x PAD
    float* WXs = sm + 2 * 64 * PAD; // 64 x PAD (per-gate slice)
    float* WHs = sm + 3 * 64 * PAD; // 64 x PAD

    const int row0 = blockIdx.x * 64;
    const int tid = threadIdx.x;
    const int tx = tid & 15, ty = tid >> 4;
    const int ld3 = 3 * D;

    for (int idx = tid; idx < 64 * 64; idx += 256) {
        int m = idx >> 6, k = idx & 63;
        int r = row0 + m;
        float a = 0.f, h = 0.f;
        if (r < E && k < D) {
            a = AG[r * 64 + k];
            h = H[r * 64 + k];
        }
        As[m * PAD + k] = a;
        Hs[m * PAD + k] = h;
    }

    float zv[4][4], rv[4][4];

    for (int g = 0; g < 3; g++) {
        __syncthreads();
        for (int idx = tid; idx < 64 * 64; idx += 256) {
            int k = idx >> 6, c = idx & 63;
            float wx = 0.f, wh = 0.f;
            if (k < D && c < D) {
                wx = Wx[k * ld3 + g * D + c];
                wh = Wh[k * ld3 + g * D + c];
            }
            WXs[k * PAD + c] = wx;
            WHs[k * PAD + c] = wh;
        }
        __syncthreads();

        float accX[4][4] = {}, accH[4][4] = {};
#pragma unroll 8
        for (int k = 0; k < 64; k++) {
            float a[4], hv[4];
#pragma unroll
            for (int i = 0; i < 4; i++) {
                a[i] = As[(ty * 4 + i) * PAD + k];
                hv[i] = Hs[(ty * 4 + i) * PAD + k];
            }
            float wx[4], wh[4];
#pragma unroll
            for (int j = 0; j < 4; j++) {
                wx[j] = WXs[k * PAD + tx * 4 + j];
                wh[j] = WHs[k * PAD + tx * 4 + j];
            }
#pragma unroll
            for (int i = 0; i < 4; i++)
#pragma unroll
                for (int j = 0; j < 4; j++) {
                    accX[i][j] += a[i] * wx[j];
                    accH[i][j] += hv[i] * wh[j];
                }
        }

#pragma unroll
        for (int i = 0; i < 4; i++) {
#pragma unroll
            for (int j = 0; j < 4; j++) {
                int c = tx * 4 + j;
                float bxv = (c < D) ? bx[g * D + c] : 0.f;
                float bhv = (c < D) ? bh[g * D + c] : 0.f;
                float gx = accX[i][j] + bxv;
                float gh = accH[i][j] + bhv;
                if (g == 0) {
                    zv[i][j] = sigm(gx + gh);
                } else if (g == 1) {
                    rv[i][j] = sigm(gx + gh);
                } else {
                    float cc = tanhf(gx + rv[i][j] * gh);
                    int r = row0 + ty * 4 + i;
                    if (r < E && c < D) {
                        float hold = Hs[(ty * 4 + i) * PAD + c];
                        H[r * 64 + c] = zv[i][j] * hold + (1.f - zv[i][j]) * cc;
                    }
                }
            }
        }
    }
}

// ---------------- readout -----------------------------------------------------
// one block per graph, thread c sums column c over the graph's edges
__global__ void k_pool2(int G) {
    int g = blockIdx.x;
    int c = threadIdx.x;
    if (c >= 123) return;
    int s = g_grow[g], n = g_gcnt[g];
    float acc = 0.f;
    for (int j = 0; j < n; j++) {
        int e = g_glist[s + j];
        acc += (c < 64) ? g_LS[(size_t)e * 64 + c] : g_NS[(size_t)e * 64 + (c - 64)];
    }
    g_pool[g * 123 + c] = acc;
}
__global__ void k_mlp(const float* __restrict__ in, int ldin, int K,
                      const float* __restrict__ W, const float* __restrict__ b,
                      int N, float* __restrict__ out, int ldout, int act) {
    __shared__ float s[256];
    int row = blockIdx.x;
    for (int k = threadIdx.x; k < K; k += blockDim.x) s[k] = in[row * ldin + k];
    __syncthreads();
    for (int t = threadIdx.x; t < N; t += blockDim.x) {
        float acc = b[t];
        for (int k = 0; k < K; k++) acc += s[k] * W[k * N + t];
        if (act) acc = seluf(acc);
        out[row * ldout + t] = acc;
    }
}

// ---------------- launch ------------------------------------------------------
extern "C" void kernel_launch(void* const* d_in, const int* in_sizes, int n_in,
                              void* d_out, int out_size) {
    int idx = 0;
    const float* graph_state = (const float*)d_in[idx++];
    const float* node_state  = (const float*)d_in[idx++];
    const int*   first       = (const int*)d_in[idx++];
    const int*   second      = (const int*)d_in[idx++];
    const int*   gids        = (const int*)d_in[idx++];
    if (idx < n_in && in_sizes[idx] == 1) idx++;   // scalar states_num_edges
    const float* W_msg  = (const float*)d_in[idx++];
    const float* b_msg  = (const float*)d_in[idx++];
    const float* Wx_e   = (const float*)d_in[idx++];
    const float* Wh_e   = (const float*)d_in[idx++];
    const float* bx_e   = (const float*)d_in[idx++];
    const float* bh_e   = (const float*)d_in[idx++];
    const float* W_nmsg = (const float*)d_in[idx++];
    const float* b_nmsg = (const float*)d_in[idx++];
    const float* Wx_n   = (const float*)d_in[idx++];
    const float* Wh_n   = (const float*)d_in[idx++];
    const float* bx_n   = (const float*)d_in[idx++];
    const float* bh_n   = (const float*)d_in[idx++];
    const float* W1     = (const float*)d_in[idx++];
    const float* b1     = (const float*)d_in[idx++];
    const float* W2     = (const float*)d_in[idx++];
    const float* b2     = (const float*)d_in[idx++];
    const float* W3     = (const float*)d_in[idx++];
    const float* b3     = (const float*)d_in[idx++];

    const int E = in_sizes[0] / 64;
    const int M = in_sizes[3];
    const int G = out_size;

    float *LS, *NS, *PQ, *AG, *POOL, *H1, *H2;
    int *CNT, *GCNT;
    cudaGetSymbolAddress((void**)&LS, g_LS);
    cudaGetSymbolAddress((void**)&NS, g_NS);
    cudaGetSymbolAddress((void**)&PQ, g_PQ);
    cudaGetSymbolAddress((void**)&AG, g_agg);
    cudaGetSymbolAddress((void**)&POOL, g_pool);
    cudaGetSymbolAddress((void**)&H1, g_h1);
    cudaGetSymbolAddress((void**)&H2, g_h2);
    cudaGetSymbolAddress((void**)&CNT, g_cnt);
    cudaGetSymbolAddress((void**)&GCNT, g_gcnt);

    const int FUSED_SMEM = 4 * 64 * PAD * (int)sizeof(float);
    cudaFuncSetAttribute(k_gru_fused, cudaFuncAttributeMaxDynamicSharedMemorySize, FUSED_SMEM);

    const int T256 = 256;
    auto gs = [](int n, int b) { return (n + b - 1) / b; };

    // init states
    k_copy_f<<<gs(E * 64, T256), T256>>>(LS, graph_state, E * 64);
    k_copy_ns<<<gs(E * 59, T256), T256>>>(node_state, E);

    // message CSR build (iteration-invariant)
    k_zero_i<<<gs(E, T256), T256>>>(CNT, E);
    k_hist<<<gs(M, T256), T256>>>(second, M);
    int nb = gs(E, 1024);
    k_scan1<<<nb, 1024>>>(E);
    k_scan2<<<1, 32>>>(nb);
    k_scan3<<<gs(E, T256), T256>>>(E);
    k_fill<<<gs(M, T256), T256>>>(first, second, M);

    // graph CSR build
    k_zero_i<<<gs(G, T256), T256>>>(GCNT, G);
    k_ghist<<<gs(E, T256), T256>>>(gids, E);
    k_gscan<<<1, G_MAX>>>(G);
    k_gfill<<<gs(E, T256), T256>>>(gids, E);

    const int rowsB = gs(E, 64);
    // ---- edge message passing: T=4 ----
    for (int t = 0; t < 4; t++) {
        k_gemm<<<dim3(rowsB, 2), 256>>>(LS, 64, E, W_msg, 64, W_msg + 64 * 64,
                                        64, 128, PQ, 128);
        k_agg<<<gs(E * 32, 256), 256>>>(E, 64, 64, b_msg);
        k_gru_fused<<<rowsB, 256, FUSED_SMEM>>>(LS, AG, Wx_e, Wh_e, bx_e, bh_e, E, 64);
    }
    // ---- node message passing: T=4 ----
    for (int t = 0; t < 4; t++) {
        k_gemm<<<dim3(rowsB, 2), 256>>>(NS, 64, E, W_nmsg, 59, W_nmsg + 59 * 59,
                                        59, 118, PQ, 128);
        k_agg<<<gs(E * 32, 256), 256>>>(E, 59, 59, b_nmsg);
        k_gru_fused<<<rowsB, 256, FUSED_SMEM>>>(NS, AG, Wx_n, Wh_n, bx_n, bh_n, E, 59);
    }

    // ---- readout ----
    k_pool2<<<G, 128>>>(G);
    k_mlp<<<G, 256>>>(POOL, 123, 123, W1, b1, 256, H1, 256, 1);
    k_mlp<<<G, 256>>>(H1, 256, 256, W2, b2, 256, H2, 256, 1);
    k_mlp<<<G, 256>>>(H2, 256, 256, W3, b3, 1, (float*)d_out, 1, 0);
}

// round 4
// speedup vs baseline: 1.4187x; 1.2327x over previous
#include <cuda_runtime.h>
#include <cuda_bf16.h>
#include <cstdint>

#define E_MAX 100000
#define M_MAX 300000
#define G_MAX 256

// ---------------- scratch (device globals; no allocations allowed) ----------
__device__ float g_LS[E_MAX * 64];     // link state, ld=64
__device__ float g_NS[E_MAX * 64];     // node state (59 used), ld=64
__device__ float g_PQ[E_MAX * 128];    // P | Q per state, ld=128
__device__ float g_agg[E_MAX * 64];    // aggregated messages, ld=64
__device__ int   g_cnt[E_MAX];
__device__ int   g_rowptr[E_MAX];
__device__ int   g_cursor[E_MAX];
__device__ int   g_csrf[M_MAX];
__device__ int   g_bsums[256];
// graph pooling CSR
__device__ int   g_gcnt[G_MAX];
__device__ int   g_grow[G_MAX];
__device__ int   g_gcur[G_MAX];
__device__ int   g_glist[E_MAX];
__device__ float g_pool[G_MAX * 123];
__device__ float g_h1[G_MAX * 256];
__device__ float g_h2[G_MAX * 256];
// GRU weight images (bf16 hi/lo), 2 sets (edge/node): [256 n][128 k] row-major
__device__ __nv_bfloat16 g_Bhi[2][256 * 128];
__device__ __nv_bfloat16 g_Blo[2][256 * 128];

// ---------------- helpers ---------------------------------------------------
__device__ __forceinline__ float seluf(float x) {
    const float sc = 1.0507009873554805f, al = 1.6732632423543772f;
    return x > 0.f ? sc * x : sc * al * (__expf(x) - 1.f);
}
__device__ __forceinline__ float sigm(float x) { return 1.f / (1.f + __expf(-x)); }

__device__ __forceinline__ void mma16816(float* c, uint32_t a0, uint32_t a1,
                                         uint32_t a2, uint32_t a3,
                                         uint32_t b0, uint32_t b1) {
    asm volatile(
        "mma.sync.aligned.m16n8k16.row.col.f32.bf16.bf16.f32 "
        "{%0,%1,%2,%3}, {%4,%5,%6,%7}, {%8,%9}, {%0,%1,%2,%3};"
        : "+f"(c[0]), "+f"(c[1]), "+f"(c[2]), "+f"(c[3])
        : "r"(a0), "r"(a1), "r"(a2), "r"(a3), "r"(b0), "r"(b1));
}

// ---------------- init / CSR build ------------------------------------------
__global__ void k_copy_f(float* dst, const float* src, int n) {
    int i = blockIdx.x * blockDim.x + threadIdx.x;
    if (i < n) dst[i] = src[i];
}
__global__ void k_copy_ns(const float* src, int E) {
    int i = blockIdx.x * blockDim.x + threadIdx.x;
    if (i < E * 59) {
        int e = i / 59, c = i % 59;
        g_NS[e * 64 + c] = src[i];
    }
}
__global__ void k_zero_i(int* p, int n) {
    int i = blockIdx.x * blockDim.x + threadIdx.x;
    if (i < n) p[i] = 0;
}
__global__ void k_hist(const int* __restrict__ second, int M) {
    int j = blockIdx.x * blockDim.x + threadIdx.x;
    if (j < M) atomicAdd(&g_cnt[second[j]], 1);
}
__global__ void k_scan1(int E) {
    __shared__ int s[1024];
    int i = blockIdx.x * 1024 + threadIdx.x;
    int v = (i < E) ? g_cnt[i] : 0;
    s[threadIdx.x] = v;
    __syncthreads();
    for (int o = 1; o < 1024; o <<= 1) {
        int t = (threadIdx.x >= o) ? s[threadIdx.x - o] : 0;
        __syncthreads();
        s[threadIdx.x] += t;
        __syncthreads();
    }
    if (i < E) g_rowptr[i] = s[threadIdx.x];
    if (threadIdx.x == 1023) g_bsums[blockIdx.x] = s[1023];
}
__global__ void k_scan2(int nb) {
    if (threadIdx.x == 0 && blockIdx.x == 0) {
        int run = 0;
        for (int b = 0; b < nb; b++) { int t = g_bsums[b]; g_bsums[b] = run; run += t; }
    }
}
__global__ void k_scan3(int E) {
    int i = blockIdx.x * blockDim.x + threadIdx.x;
    if (i < E) {
        int ex = g_rowptr[i] - g_cnt[i] + g_bsums[i / 1024];
        g_rowptr[i] = ex;
        g_cursor[i] = ex;
    }
}
__global__ void k_fill(const int* __restrict__ first, const int* __restrict__ second, int M) {
    int j = blockIdx.x * blockDim.x + threadIdx.x;
    if (j < M) {
        int pos = atomicAdd(&g_cursor[second[j]], 1);
        g_csrf[pos] = first[j];
    }
}
__global__ void k_ghist(const int* __restrict__ gid, int E) {
    int i = blockIdx.x * blockDim.x + threadIdx.x;
    if (i < E) atomicAdd(&g_gcnt[gid[i]], 1);
}
__global__ void k_gscan(int G) {
    __shared__ int s[G_MAX];
    int t = threadIdx.x;
    s[t] = (t < G) ? g_gcnt[t] : 0;
    __syncthreads();
    for (int o = 1; o < G_MAX; o <<= 1) {
        int v = (t >= o) ? s[t - o] : 0;
        __syncthreads();
        s[t] += v;
        __syncthreads();
    }
    if (t < G) {
        int ex = s[t] - g_gcnt[t];
        g_grow[t] = ex;
        g_gcur[t] = ex;
    }
}
__global__ void k_gfill(const int* __restrict__ gid, int E) {
    int i = blockIdx.x * blockDim.x + threadIdx.x;
    if (i < E) {
        int pos = atomicAdd(&g_gcur[gid[i]], 1);
        g_glist[pos] = i;
    }
}

// ---------------- build GRU weight images (hi/lo bf16) -----------------------
// B[n][k]: n = gate*64 + c (gates z,r,xh,hh); k = 0..63 agg input, 64..127 h.
__global__ void k_buildB(const float* __restrict__ Wx, const float* __restrict__ Wh,
                         int D, int set) {
    int idx = blockIdx.x * blockDim.x + threadIdx.x;
    if (idx >= 256 * 128) return;
    int n = idx >> 7, k = idx & 127;
    int ld3 = 3 * D;
    float v = 0.f;
    if (n < 128) {                       // z (n<64) and r (64<=n<128): Wx | Wh
        int g = n >> 6, c = n & 63;
        if (c < D) {
            if (k < 64) { if (k < D) v = Wx[k * ld3 + g * D + c]; }
            else { int kk = k - 64; if (kk < D) v = Wh[kk * ld3 + g * D + c]; }
        }
    } else if (n < 192) {                // xh: Wx only
        int c = n - 128;
        if (c < D && k < 64 && k < D) v = Wx[k * ld3 + 2 * D + c];
    } else {                             // hh: Wh only
        int c = n - 192, kk = k - 64;
        if (c < D && k >= 64 && kk < D) v = Wh[kk * ld3 + 2 * D + c];
    }
    __nv_bfloat16 hi = __float2bfloat16(v);
    __nv_bfloat16 lo = __float2bfloat16(v - __bfloat162float(hi));
    g_Bhi[set][idx] = hi;
    g_Blo[set][idx] = lo;
}

// ---------------- tiled fp32 GEMM: C[rows,N] = A[rows,K] @ W ------------------
__global__ void k_gemm(const float* __restrict__ A, int lda, int rows,
                       const float* __restrict__ W0, int n0,
                       const float* __restrict__ W1,
                       int K, int N, float* __restrict__ C, int ldc) {
    __shared__ float As[64 * 68];
    __shared__ float Ws[64 * 64];
    const int row0 = blockIdx.x * 64, col0 = blockIdx.y * 64;
    const int tid = threadIdx.x;
    const int n1 = N - n0;

    for (int idx = tid; idx < 64 * K; idx += 256) {
        int m = idx / K, k = idx % K;
        int r = row0 + m;
        As[m * 68 + k] = (r < rows) ? A[r * lda + k] : 0.f;
    }
    for (int idx = tid; idx < K * 64; idx += 256) {
        int k = idx / 64, c = idx % 64;
        int gc = col0 + c;
        float w = 0.f;
        if (gc < N) w = (gc < n0) ? W0[k * n0 + gc] : W1[k * n1 + (gc - n0)];
        Ws[k * 64 + c] = w;
    }
    __syncthreads();

    const int tx = tid & 15, ty = tid >> 4;
    float acc[4][4] = {};
#pragma unroll 8
    for (int k = 0; k < K; k++) {
        float a[4];
#pragma unroll
        for (int i = 0; i < 4; i++) a[i] = As[(ty * 4 + i) * 68 + k];
        float4 b = *(const float4*)&Ws[k * 64 + tx * 4];
#pragma unroll
        for (int i = 0; i < 4; i++) {
            acc[i][0] += a[i] * b.x;
            acc[i][1] += a[i] * b.y;
            acc[i][2] += a[i] * b.z;
            acc[i][3] += a[i] * b.w;
        }
    }
#pragma unroll
    for (int i = 0; i < 4; i++) {
        int r = row0 + ty * 4 + i;
        if (r >= rows) continue;
#pragma unroll
        for (int j = 0; j < 4; j++) {
            int gc = col0 + tx * 4 + j;
            if (gc < N) C[r * ldc + gc] = acc[i][j];
        }
    }
}

// ---------------- message aggregation (CSR, warp per target) -----------------
__global__ void k_agg(int E, int D, int qOff, const float* __restrict__ bias) {
    int w = (blockIdx.x * blockDim.x + threadIdx.x) >> 5;
    if (w >= E) return;
    int lane = threadIdx.x & 31;
    int c0 = lane, c1 = lane + 32;
    bool v1 = (c1 < D);
    float q0 = g_PQ[w * 128 + qOff + c0] + bias[c0];
    float q1 = v1 ? (g_PQ[w * 128 + qOff + c1] + bias[c1]) : 0.f;
    float a0 = 0.f, a1 = 0.f;
    int s = g_rowptr[w], n = g_cnt[w];
    int i = 0;
    for (; i + 2 <= n; i += 2) {
        int f0 = g_csrf[s + i], f1 = g_csrf[s + i + 1];
        const float* p0 = g_PQ + (size_t)f0 * 128;
        const float* p1 = g_PQ + (size_t)f1 * 128;
        float x00 = p0[c0], x10 = p1[c0];
        float x01 = v1 ? p0[c1] : 0.f, x11 = v1 ? p1[c1] : 0.f;
        a0 += seluf(x00 + q0) + seluf(x10 + q0);
        if (v1) a1 += seluf(x01 + q1) + seluf(x11 + q1);
    }
    for (; i < n; i++) {
        int f = g_csrf[s + i];
        const float* p = g_PQ + (size_t)f * 128;
        a0 += seluf(p[c0] + q0);
        if (v1) a1 += seluf(p[c1] + q1);
    }
    g_agg[w * 64 + c0] = a0;
    if (v1) g_agg[w * 64 + c1] = a1;
}

// ---------------- fused GRU via warp-level mma.sync (bf16 split, 3-pass) -----
// Block: 128 rows (8 row-warp-groups x 16), 512 threads (16 warps: 8 row x 2 ci-half).
// gates[128x256] = [agg|h](128x128) @ B^T; GRU epilogue from fragments.
// smem (uint32 units): Ahi[128][68], Alo[128][68], Bhi[256][68], Blo[256][68]
#define APITCH 68
#define SM_AHI 0
#define SM_ALO (128 * APITCH)
#define SM_BHI (2 * 128 * APITCH)
#define SM_BLO (2 * 128 * APITCH + 256 * APITCH)
#define SM_MMA_BYTES ((2 * 128 + 2 * 256) * APITCH * 4)

__global__ void __launch_bounds__(512, 1) k_gru_mma(
        float* __restrict__ H, const float* __restrict__ AG,
        const float* __restrict__ bx, const float* __restrict__ bh,
        int E, int D, int set) {
    extern __shared__ uint32_t sm[];
    const int tid = threadIdx.x;
    const int wid = tid >> 5, lane = tid & 31;
    const int wrow = wid & 7, whalf = wid >> 3;
    const int gq = lane >> 2, tig = lane & 3;
    const int row0 = blockIdx.x * 128;

    // ---- build A hi/lo (pairs of bf16 per uint32) ----
    for (int idx = tid; idx < 128 * 64; idx += 512) {
        int m = idx >> 6, kp = idx & 63;     // element cols 2kp, 2kp+1
        int r = row0 + m;
        float v0 = 0.f, v1 = 0.f;
        if (r < E) {
            int k0 = kp * 2, k1 = kp * 2 + 1;
            if (k0 < 64) { if (k0 < D) v0 = AG[r * 64 + k0]; }
            else { int kk = k0 - 64; if (kk < D) v0 = H[r * 64 + kk]; }
            if (k1 < 64) { if (k1 < D) v1 = AG[r * 64 + k1]; }
            else { int kk = k1 - 64; if (kk < D) v1 = H[r * 64 + kk]; }
        }
        __nv_bfloat16 h0 = __float2bfloat16(v0), h1 = __float2bfloat16(v1);
        __nv_bfloat16 l0 = __float2bfloat16(v0 - __bfloat162float(h0));
        __nv_bfloat16 l1 = __float2bfloat16(v1 - __bfloat162float(h1));
        uint32_t hv = ((uint32_t)__bfloat16_as_ushort(h1) << 16) | __bfloat16_as_ushort(h0);
        uint32_t lv = ((uint32_t)__bfloat16_as_ushort(l1) << 16) | __bfloat16_as_ushort(l0);
        sm[SM_AHI + m * APITCH + kp] = hv;
        sm[SM_ALO + m * APITCH + kp] = lv;
    }
    // ---- copy B hi/lo images ----
    {
        const uint32_t* bhsrc = (const uint32_t*)(g_Bhi[set]);
        const uint32_t* blsrc = (const uint32_t*)(g_Blo[set]);
        for (int idx = tid; idx < 256 * 64; idx += 512) {
            int n = idx >> 6, kp = idx & 63;
            sm[SM_BHI + n * APITCH + kp] = bhsrc[idx];
            sm[SM_BLO + n * APITCH + kp] = blsrc[idx];
        }
    }
    __syncthreads();

    const int mrow = wrow * 16;   // local row base for this warp

    for (int ci = whalf * 2; ci < whalf * 2 + 2; ci++) {
        float acc[4][2][4];
#pragma unroll
        for (int g4 = 0; g4 < 4; g4++)
#pragma unroll
            for (int nt = 0; nt < 2; nt++)
#pragma unroll
                for (int q = 0; q < 4; q++) acc[g4][nt][q] = 0.f;

#pragma unroll
        for (int kt = 0; kt < 8; kt++) {
            int kp = kt * 8 + tig;
            uint32_t ah0 = sm[SM_AHI + (mrow + gq) * APITCH + kp];
            uint32_t ah1 = sm[SM_AHI + (mrow + gq + 8) * APITCH + kp];
            uint32_t ah2 = sm[SM_AHI + (mrow + gq) * APITCH + kp + 4];
            uint32_t ah3 = sm[SM_AHI + (mrow + gq + 8) * APITCH + kp + 4];
            uint32_t al0 = sm[SM_ALO + (mrow + gq) * APITCH + kp];
            uint32_t al1 = sm[SM_ALO + (mrow + gq + 8) * APITCH + kp];
            uint32_t al2 = sm[SM_ALO + (mrow + gq) * APITCH + kp + 4];
            uint32_t al3 = sm[SM_ALO + (mrow + gq + 8) * APITCH + kp + 4];
#pragma unroll
            for (int g4 = 0; g4 < 4; g4++) {
#pragma unroll
                for (int nt = 0; nt < 2; nt++) {
                    int n = g4 * 64 + ci * 16 + nt * 8 + gq;
                    uint32_t bh0 = sm[SM_BHI + n * APITCH + kp];
                    uint32_t bh1 = sm[SM_BHI + n * APITCH + kp + 4];
                    uint32_t bl0 = sm[SM_BLO + n * APITCH + kp];
                    uint32_t bl1 = sm[SM_BLO + n * APITCH + kp + 4];
                    mma16816(acc[g4][nt], ah0, ah1, ah2, ah3, bh0, bh1);
                    mma16816(acc[g4][nt], ah0, ah1, ah2, ah3, bl0, bl1);
                    mma16816(acc[g4][nt], al0, al1, al2, al3, bh0, bh1);
                }
            }
        }

        // ---- GRU epilogue from fragments ----
        int r0 = row0 + mrow + gq;
        int r1 = r0 + 8;
#pragma unroll
        for (int nt = 0; nt < 2; nt++) {
#pragma unroll
            for (int half = 0; half < 2; half++) {
                int c = ci * 16 + nt * 8 + tig * 2 + half;
                if (c >= D) continue;
                float bzs = bx[c] + bh[c];
                float brs = bx[D + c] + bh[D + c];
                float bxh = bx[2 * D + c];
                float bhh = bh[2 * D + c];
                // row r0 -> frag idx half; row r1 -> frag idx 2+half
                if (r0 < E) {
                    float z = sigm(acc[0][nt][half] + bzs);
                    float rr = sigm(acc[1][nt][half] + brs);
                    float cand = tanhf(acc[2][nt][half] + bxh +
                                       rr * (acc[3][nt][half] + bhh));
                    float hold = H[r0 * 64 + c];
                    H[r0 * 64 + c] = z * hold + (1.f - z) * cand;
                }
                if (r1 < E) {
                    float z = sigm(acc[0][nt][2 + half] + bzs);
                    float rr = sigm(acc[1][nt][2 + half] + brs);
                    float cand = tanhf(acc[2][nt][2 + half] + bxh +
                                       rr * (acc[3][nt][2 + half] + bhh));
                    float hold = H[r1 * 64 + c];
                    H[r1 * 64 + c] = z * hold + (1.f - z) * cand;
                }
            }
        }
    }
}

// ---------------- readout -----------------------------------------------------
__global__ void k_pool2(int G) {
    int g = blockIdx.x;
    int c = threadIdx.x;
    if (c >= 123) return;
    int s = g_grow[g], n = g_gcnt[g];
    float acc = 0.f;
    for (int j = 0; j < n; j++) {
        int e = g_glist[s + j];
        acc += (c < 64) ? g_LS[(size_t)e * 64 + c] : g_NS[(size_t)e * 64 + (c - 64)];
    }
    g_pool[g * 123 + c] = acc;
}
__global__ void k_mlp(const float* __restrict__ in, int ldin, int K,
                      const float* __restrict__ W, const float* __restrict__ b,
                      int N, float* __restrict__ out, int ldout, int act) {
    __shared__ float s[256];
    int row = blockIdx.x;
    for (int k = threadIdx.x; k < K; k += blockDim.x) s[k] = in[row * ldin + k];
    __syncthreads();
    for (int t = threadIdx.x; t < N; t += blockDim.x) {
        float acc = b[t];
        for (int k = 0; k < K; k++) acc += s[k] * W[k * N + t];
        if (act) acc = seluf(acc);
        out[row * ldout + t] = acc;
    }
}

// ---------------- launch ------------------------------------------------------
extern "C" void kernel_launch(void* const* d_in, const int* in_sizes, int n_in,
                              void* d_out, int out_size) {
    int idx = 0;
    const float* graph_state = (const float*)d_in[idx++];
    const float* node_state  = (const float*)d_in[idx++];
    const int*   first       = (const int*)d_in[idx++];
    const int*   second      = (const int*)d_in[idx++];
    const int*   gids        = (const int*)d_in[idx++];
    if (idx < n_in && in_sizes[idx] == 1) idx++;   // scalar states_num_edges
    const float* W_msg  = (const float*)d_in[idx++];
    const float* b_msg  = (const float*)d_in[idx++];
    const float* Wx_e   = (const float*)d_in[idx++];
    const float* Wh_e   = (const float*)d_in[idx++];
    const float* bx_e   = (const float*)d_in[idx++];
    const float* bh_e   = (const float*)d_in[idx++];
    const float* W_nmsg = (const float*)d_in[idx++];
    const float* b_nmsg = (const float*)d_in[idx++];
    const float* Wx_n   = (const float*)d_in[idx++];
    const float* Wh_n   = (const float*)d_in[idx++];
    const float* bx_n   = (const float*)d_in[idx++];
    const float* bh_n   = (const float*)d_in[idx++];
    const float* W1     = (const float*)d_in[idx++];
    const float* b1     = (const float*)d_in[idx++];
    const float* W2     = (const float*)d_in[idx++];
    const float* b2     = (const float*)d_in[idx++];
    const float* W3     = (const float*)d_in[idx++];
    const float* b3     = (const float*)d_in[idx++];

    const int E = in_sizes[0] / 64;
    const int M = in_sizes[3];
    const int G = out_size;

    float *LS, *NS, *PQ, *AG, *POOL, *H1, *H2;
    int *CNT, *GCNT;
    cudaGetSymbolAddress((void**)&LS, g_LS);
    cudaGetSymbolAddress((void**)&NS, g_NS);
    cudaGetSymbolAddress((void**)&PQ, g_PQ);
    cudaGetSymbolAddress((void**)&AG, g_agg);
    cudaGetSymbolAddress((void**)&POOL, g_pool);
    cudaGetSymbolAddress((void**)&H1, g_h1);
    cudaGetSymbolAddress((void**)&H2, g_h2);
    cudaGetSymbolAddress((void**)&CNT, g_cnt);
    cudaGetSymbolAddress((void**)&GCNT, g_gcnt);

    cudaFuncSetAttribute(k_gru_mma, cudaFuncAttributeMaxDynamicSharedMemorySize,
                         SM_MMA_BYTES);

    const int T256 = 256;
    auto gs = [](int n, int b) { return (n + b - 1) / b; };

    // init states
    k_copy_f<<<gs(E * 64, T256), T256>>>(LS, graph_state, E * 64);
    k_copy_ns<<<gs(E * 59, T256), T256>>>(node_state, E);

    // GRU weight images (once; weights constant across iterations)
    k_buildB<<<gs(256 * 128, T256), T256>>>(Wx_e, Wh_e, 64, 0);
    k_buildB<<<gs(256 * 128, T256), T256>>>(Wx_n, Wh_n, 59, 1);

    // message CSR build (iteration-invariant)
    k_zero_i<<<gs(E, T256), T256>>>(CNT, E);
    k_hist<<<gs(M, T256), T256>>>(second, M);
    int nb = gs(E, 1024);
    k_scan1<<<nb, 1024>>>(E);
    k_scan2<<<1, 32>>>(nb);
    k_scan3<<<gs(E, T256), T256>>>(E);
    k_fill<<<gs(M, T256), T256>>>(first, second, M);

    // graph CSR build
    k_zero_i<<<gs(G, T256), T256>>>(GCNT, G);
    k_ghist<<<gs(E, T256), T256>>>(gids, E);
    k_gscan<<<1, G_MAX>>>(G);
    k_gfill<<<gs(E, T256), T256>>>(gids, E);

    const int rowsB = gs(E, 64);
    const int rowsMMA = gs(E, 128);
    // ---- edge message passing: T=4 ----
    for (int t = 0; t < 4; t++) {
        k_gemm<<<dim3(rowsB, 2), 256>>>(LS, 64, E, W_msg, 64, W_msg + 64 * 64,
                                        64, 128, PQ, 128);
        k_agg<<<gs(E * 32, 256), 256>>>(E, 64, 64, b_msg);
        k_gru_mma<<<rowsMMA, 512, SM_MMA_BYTES>>>(LS, AG, bx_e, bh_e, E, 64, 0);
    }
    // ---- node message passing: T=4 ----
    for (int t = 0; t < 4; t++) {
        k_gemm<<<dim3(rowsB, 2), 256>>>(NS, 64, E, W_nmsg, 59, W_nmsg + 59 * 59,
                                        59, 118, PQ, 128);
        k_agg<<<gs(E * 32, 256), 256>>>(E, 59, 59, b_nmsg);
        k_gru_mma<<<rowsMMA, 512, SM_MMA_BYTES>>>(NS, AG, bx_n, bh_n, E, 59, 1);
    }

    // ---- readout ----
    k_pool2<<<G, 128>>>(G);
    k_mlp<<<G, 256>>>(POOL, 123, 123, W1, b1, 256, H1, 256, 1);
    k_mlp<<<G, 256>>>(H1, 256, 256, W2, b2, 256, H2, 256, 1);
    k_mlp<<<G, 256>>>(H2, 256, 256, W3, b3, 1, (float*)d_out, 1, 0);
}

// round 5
// speedup vs baseline: 1.5505x; 1.0929x over previous
#include <cuda_runtime.h>
#include <cuda_bf16.h>
#include <cstdint>

#define E_MAX 100000
#define M_MAX 300000
#define G_MAX 256

// ---------------- scratch (device globals; no allocations allowed) ----------
__device__ float g_LS[E_MAX * 64];     // link state, ld=64
__device__ float g_NS[E_MAX * 64];     // node state (59 used), ld=64
__device__ float g_PQ[E_MAX * 128];    // P | Q per state: P[0,64), Q[64,128)
__device__ float g_agg[E_MAX * 64];    // aggregated messages, ld=64
__device__ int   g_cnt[E_MAX];
__device__ int   g_rowptr[E_MAX];
__device__ int   g_cursor[E_MAX];
__device__ int   g_csrf[M_MAX];
__device__ int   g_bsums[256];
// graph pooling CSR
__device__ int   g_gcnt[G_MAX];
__device__ int   g_grow[G_MAX];
__device__ int   g_gcur[G_MAX];
__device__ int   g_glist[E_MAX];
__device__ float g_pool[G_MAX * 123];
__device__ float g_h1[G_MAX * 256];
__device__ float g_h2[G_MAX * 256];
// GRU weight images (bf16 hi/lo), 2 sets (edge/node): [256 n][128 k] row-major
__device__ __nv_bfloat16 g_Bhi[2][256 * 128];
__device__ __nv_bfloat16 g_Blo[2][256 * 128];
// PQ projection weight images (bf16 hi/lo): [128 n][64 k]
__device__ __nv_bfloat16 g_Phi[2][128 * 64];
__device__ __nv_bfloat16 g_Plo[2][128 * 64];

// ---------------- helpers ---------------------------------------------------
__device__ __forceinline__ float seluf(float x) {
    const float sc = 1.0507009873554805f, al = 1.6732632423543772f;
    return x > 0.f ? sc * x : sc * al * (__expf(x) - 1.f);
}
__device__ __forceinline__ float sigm(float x) { return 1.f / (1.f + __expf(-x)); }

__device__ __forceinline__ void mma16816(float* c, uint32_t a0, uint32_t a1,
                                         uint32_t a2, uint32_t a3,
                                         uint32_t b0, uint32_t b1) {
    asm volatile(
        "mma.sync.aligned.m16n8k16.row.col.f32.bf16.bf16.f32 "
        "{%0,%1,%2,%3}, {%4,%5,%6,%7}, {%8,%9}, {%0,%1,%2,%3};"
        : "+f"(c[0]), "+f"(c[1]), "+f"(c[2]), "+f"(c[3])
        : "r"(a0), "r"(a1), "r"(a2), "r"(a3), "r"(b0), "r"(b1));
}

__device__ __forceinline__ uint32_t pack_bf16(float v0, float v1,
                                              uint32_t* lo) {
    __nv_bfloat16 h0 = __float2bfloat16(v0), h1 = __float2bfloat16(v1);
    __nv_bfloat16 l0 = __float2bfloat16(v0 - __bfloat162float(h0));
    __nv_bfloat16 l1 = __float2bfloat16(v1 - __bfloat162float(h1));
    *lo = ((uint32_t)__bfloat16_as_ushort(l1) << 16) | __bfloat16_as_ushort(l0);
    return ((uint32_t)__bfloat16_as_ushort(h1) << 16) | __bfloat16_as_ushort(h0);
}

// ---------------- init / CSR build ------------------------------------------
__global__ void k_copy_f(float* dst, const float* src, int n) {
    int i = blockIdx.x * blockDim.x + threadIdx.x;
    if (i < n) dst[i] = src[i];
}
__global__ void k_copy_ns(const float* src, int E) {
    int i = blockIdx.x * blockDim.x + threadIdx.x;
    if (i < E * 59) {
        int e = i / 59, c = i % 59;
        g_NS[e * 64 + c] = src[i];
    }
}
__global__ void k_zero_i(int* p, int n) {
    int i = blockIdx.x * blockDim.x + threadIdx.x;
    if (i < n) p[i] = 0;
}
__global__ void k_hist(const int* __restrict__ second, int M) {
    int j = blockIdx.x * blockDim.x + threadIdx.x;
    if (j < M) atomicAdd(&g_cnt[second[j]], 1);
}
__global__ void k_scan1(int E) {
    __shared__ int s[1024];
    int i = blockIdx.x * 1024 + threadIdx.x;
    int v = (i < E) ? g_cnt[i] : 0;
    s[threadIdx.x] = v;
    __syncthreads();
    for (int o = 1; o < 1024; o <<= 1) {
        int t = (threadIdx.x >= o) ? s[threadIdx.x - o] : 0;
        __syncthreads();
        s[threadIdx.x] += t;
        __syncthreads();
    }
    if (i < E) g_rowptr[i] = s[threadIdx.x];
    if (threadIdx.x == 1023) g_bsums[blockIdx.x] = s[1023];
}
__global__ void k_scan2(int nb) {
    if (threadIdx.x == 0 && blockIdx.x == 0) {
        int run = 0;
        for (int b = 0; b < nb; b++) { int t = g_bsums[b]; g_bsums[b] = run; run += t; }
    }
}
__global__ void k_scan3(int E) {
    int i = blockIdx.x * blockDim.x + threadIdx.x;
    if (i < E) {
        int ex = g_rowptr[i] - g_cnt[i] + g_bsums[i / 1024];
        g_rowptr[i] = ex;
        g_cursor[i] = ex;
    }
}
__global__ void k_fill(const int* __restrict__ first, const int* __restrict__ second, int M) {
    int j = blockIdx.x * blockDim.x + threadIdx.x;
    if (j < M) {
        int pos = atomicAdd(&g_cursor[second[j]], 1);
        g_csrf[pos] = first[j];
    }
}
__global__ void k_ghist(const int* __restrict__ gid, int E) {
    int i = blockIdx.x * blockDim.x + threadIdx.x;
    if (i < E) atomicAdd(&g_gcnt[gid[i]], 1);
}
__global__ void k_gscan(int G) {
    __shared__ int s[G_MAX];
    int t = threadIdx.x;
    s[t] = (t < G) ? g_gcnt[t] : 0;
    __syncthreads();
    for (int o = 1; o < G_MAX; o <<= 1) {
        int v = (t >= o) ? s[t - o] : 0;
        __syncthreads();
        s[t] += v;
        __syncthreads();
    }
    if (t < G) {
        int ex = s[t] - g_gcnt[t];
        g_grow[t] = ex;
        g_gcur[t] = ex;
    }
}
__global__ void k_gfill(const int* __restrict__ gid, int E) {
    int i = blockIdx.x * blockDim.x + threadIdx.x;
    if (i < E) {
        int pos = atomicAdd(&g_gcur[gid[i]], 1);
        g_glist[pos] = i;
    }
}

// ---------------- build GRU weight images (hi/lo bf16) -----------------------
// B[n][k]: n = gate*64 + c (gates z,r,xh,hh); k = 0..63 agg input, 64..127 h.
__global__ void k_buildB(const float* __restrict__ Wx, const float* __restrict__ Wh,
                         int D, int set) {
    int idx = blockIdx.x * blockDim.x + threadIdx.x;
    if (idx >= 256 * 128) return;
    int n = idx >> 7, k = idx & 127;
    int ld3 = 3 * D;
    float v = 0.f;
    if (n < 128) {                       // z (n<64) and r (64<=n<128): Wx | Wh
        int g = n >> 6, c = n & 63;
        if (c < D) {
            if (k < 64) { if (k < D) v = Wx[k * ld3 + g * D + c]; }
            else { int kk = k - 64; if (kk < D) v = Wh[kk * ld3 + g * D + c]; }
        }
    } else if (n < 192) {                // xh: Wx only
        int c = n - 128;
        if (c < D && k < 64 && k < D) v = Wx[k * ld3 + 2 * D + c];
    } else {                             // hh: Wh only
        int c = n - 192, kk = k - 64;
        if (c < D && k >= 64 && kk < D) v = Wh[kk * ld3 + 2 * D + c];
    }
    __nv_bfloat16 hi = __float2bfloat16(v);
    __nv_bfloat16 lo = __float2bfloat16(v - __bfloat162float(hi));
    g_Bhi[set][idx] = hi;
    g_Blo[set][idx] = lo;
}

// PQ projection weights: Bpq[n][k]: n<64 -> P col n = W[k][n]; n>=64 -> Q col
// (n-64) = W[D+k][n-64]. W is [2D][D] row-major. Zeros outside valid range.
__global__ void k_buildBpq(const float* __restrict__ W, int D, int set) {
    int idx = blockIdx.x * blockDim.x + threadIdx.x;
    if (idx >= 128 * 64) return;
    int n = idx >> 6, k = idx & 63;
    float v = 0.f;
    if (k < D) {
        if (n < 64) { if (n < D) v = W[k * D + n]; }
        else { int c = n - 64; if (c < D) v = W[(D + k) * D + c]; }
    }
    __nv_bfloat16 hi = __float2bfloat16(v);
    __nv_bfloat16 lo = __float2bfloat16(v - __bfloat162float(hi));
    g_Phi[set][idx] = hi;
    g_Plo[set][idx] = lo;
}

// ---------------- message aggregation (CSR, warp per target) -----------------
// agg[e,c] = sum_{j: second[j]==e} selu(P[first[j],c] + Q[e,c] + bias[c])
__global__ void k_agg(int E, int D, const float* __restrict__ bias) {
    int w = (blockIdx.x * blockDim.x + threadIdx.x) >> 5;
    if (w >= E) return;
    int lane = threadIdx.x & 31;
    int c0 = lane, c1 = lane + 32;
    bool v1 = (c1 < D);
    float q0 = g_PQ[w * 128 + 64 + c0] + bias[c0];
    float q1 = v1 ? (g_PQ[w * 128 + 64 + c1] + bias[c1]) : 0.f;
    float a0 = 0.f, a1 = 0.f;
    int s = g_rowptr[w], n = g_cnt[w];
    int i = 0;
    for (; i + 2 <= n; i += 2) {
        int f0 = g_csrf[s + i], f1 = g_csrf[s + i + 1];
        const float* p0 = g_PQ + (size_t)f0 * 128;
        const float* p1 = g_PQ + (size_t)f1 * 128;
        float x00 = p0[c0], x10 = p1[c0];
        float x01 = v1 ? p0[c1] : 0.f, x11 = v1 ? p1[c1] : 0.f;
        a0 += seluf(x00 + q0) + seluf(x10 + q0);
        if (v1) a1 += seluf(x01 + q1) + seluf(x11 + q1);
    }
    for (; i < n; i++) {
        int f = g_csrf[s + i];
        const float* p = g_PQ + (size_t)f * 128;
        a0 += seluf(p[c0] + q0);
        if (v1) a1 += seluf(p[c1] + q1);
    }
    g_agg[w * 64 + c0] = a0;
    if (v1) g_agg[w * 64 + c1] = a1;
}

// ---------------- fused iteration kernel --------------------------------------
// mode 0 (full): GRU update of H from (agg|H) via mma.sync, then (do_pq)
//   PQ = Hnew @ Bpq^T, all tensor-core, split-bf16 3-pass.
// mode 1 (init): PQ = H @ Bpq^T only.
// Block = 128 rows, 512 threads (16 warps: 8 row-groups x 2 col-halves).
#define APITCH 68
#define BPITCH 36
#define SM_AHI 0
#define SM_ALO (128 * APITCH)
#define SM_B (2 * 128 * APITCH)
#define SM_BLO_G (SM_B + 256 * APITCH)
#define SM_BLO_P (SM_B + 128 * BPITCH)
#define SM_BYTES ((2 * 128 * APITCH + 2 * 256 * APITCH) * 4)

__global__ void __launch_bounds__(512, 1) k_iter(
        float* __restrict__ H, const float* __restrict__ bx,
        const float* __restrict__ bh, int E, int D, int set,
        int mode, int do_pq) {
    extern __shared__ uint32_t sm[];
    const int tid = threadIdx.x;
    const int wid = tid >> 5, lane = tid & 31;
    const int wrow = wid & 7, whalf = wid >> 3;
    const int gq = lane >> 2, tig = lane & 3;
    const int row0 = blockIdx.x * 128;
    const int mrow = wrow * 16;

    if (mode == 1) {
        // build A = state (128 x 64) hi/lo
        for (int idx = tid; idx < 128 * 32; idx += 512) {
            int m = idx >> 5, kp = idx & 31;
            int r = row0 + m;
            float v0 = 0.f, v1 = 0.f;
            int k0 = kp * 2, k1 = k0 + 1;
            if (r < E) {
                if (k0 < D) v0 = H[r * 64 + k0];
                if (k1 < D) v1 = H[r * 64 + k1];
            }
            uint32_t lo, hi = pack_bf16(v0, v1, &lo);
            sm[SM_AHI + m * APITCH + kp] = hi;
            sm[SM_ALO + m * APITCH + kp] = lo;
        }
    } else {
        // ---- build A = [agg | H] (128 x 128) hi/lo ----
        for (int idx = tid; idx < 128 * 64; idx += 512) {
            int m = idx >> 6, kp = idx & 63;
            int r = row0 + m;
            float v0 = 0.f, v1 = 0.f;
            if (r < E) {
                int k0 = kp * 2, k1 = k0 + 1;
                if (k0 < 64) { if (k0 < D) v0 = g_agg[r * 64 + k0]; }
                else { int kk = k0 - 64; if (kk < D) v0 = H[r * 64 + kk]; }
                if (k1 < 64) { if (k1 < D) v1 = g_agg[r * 64 + k1]; }
                else { int kk = k1 - 64; if (kk < D) v1 = H[r * 64 + kk]; }
            }
            uint32_t lo, hi = pack_bf16(v0, v1, &lo);
            sm[SM_AHI + m * APITCH + kp] = hi;
            sm[SM_ALO + m * APITCH + kp] = lo;
        }
        // ---- copy GRU B images ----
        {
            const uint32_t* bhsrc = (const uint32_t*)(g_Bhi[set]);
            const uint32_t* blsrc = (const uint32_t*)(g_Blo[set]);
            for (int idx = tid; idx < 256 * 64; idx += 512) {
                int n = idx >> 6, kp = idx & 63;
                sm[SM_B + n * APITCH + kp] = bhsrc[idx];
                sm[SM_BLO_G + n * APITCH + kp] = blsrc[idx];
            }
        }
        __syncthreads();

        uint32_t stH[2][2][2], stL[2][2][2];

        for (int ci_i = 0; ci_i < 2; ci_i++) {
            int ci = whalf * 2 + ci_i;
            float acc[4][2][4];
#pragma unroll
            for (int g4 = 0; g4 < 4; g4++)
#pragma unroll
                for (int nt = 0; nt < 2; nt++)
#pragma unroll
                    for (int q = 0; q < 4; q++) acc[g4][nt][q] = 0.f;

#pragma unroll
            for (int kt = 0; kt < 8; kt++) {
                int kp = kt * 8 + tig;
                uint32_t ah0 = sm[SM_AHI + (mrow + gq) * APITCH + kp];
                uint32_t ah1 = sm[SM_AHI + (mrow + gq + 8) * APITCH + kp];
                uint32_t ah2 = sm[SM_AHI + (mrow + gq) * APITCH + kp + 4];
                uint32_t ah3 = sm[SM_AHI + (mrow + gq + 8) * APITCH + kp + 4];
                uint32_t al0 = sm[SM_ALO + (mrow + gq) * APITCH + kp];
                uint32_t al1 = sm[SM_ALO + (mrow + gq + 8) * APITCH + kp];
                uint32_t al2 = sm[SM_ALO + (mrow + gq) * APITCH + kp + 4];
                uint32_t al3 = sm[SM_ALO + (mrow + gq + 8) * APITCH + kp + 4];
#pragma unroll
                for (int g4 = 0; g4 < 4; g4++) {
#pragma unroll
                    for (int nt = 0; nt < 2; nt++) {
                        int n = g4 * 64 + ci * 16 + nt * 8 + gq;
                        uint32_t bh0 = sm[SM_B + n * APITCH + kp];
                        uint32_t bh1 = sm[SM_B + n * APITCH + kp + 4];
                        uint32_t bl0 = sm[SM_BLO_G + n * APITCH + kp];
                        uint32_t bl1 = sm[SM_BLO_G + n * APITCH + kp + 4];
                        mma16816(acc[g4][nt], ah0, ah1, ah2, ah3, bh0, bh1);
                        mma16816(acc[g4][nt], ah0, ah1, ah2, ah3, bl0, bl1);
                        mma16816(acc[g4][nt], al0, al1, al2, al3, bh0, bh1);
                    }
                }
            }

            // GRU epilogue: write H, stash Hnew bf16 pairs for PQ phase
#pragma unroll
            for (int nt = 0; nt < 2; nt++) {
#pragma unroll
                for (int rh = 0; rh < 2; rh++) {
                    int r = row0 + mrow + gq + rh * 8;
                    int c0 = ci * 16 + nt * 8 + tig * 2;
                    float h0 = 0.f, h1 = 0.f;
                    if (r < E) {
                        if (c0 < D) {
                            float z = sigm(acc[0][nt][rh * 2] + bx[c0] + bh[c0]);
                            float rr = sigm(acc[1][nt][rh * 2] + bx[D + c0] + bh[D + c0]);
                            float cand = tanhf(acc[2][nt][rh * 2] + bx[2 * D + c0] +
                                               rr * (acc[3][nt][rh * 2] + bh[2 * D + c0]));
                            h0 = z * H[r * 64 + c0] + (1.f - z) * cand;
                        }
                        if (c0 + 1 < D) {
                            int c = c0 + 1;
                            float z = sigm(acc[0][nt][rh * 2 + 1] + bx[c] + bh[c]);
                            float rr = sigm(acc[1][nt][rh * 2 + 1] + bx[D + c] + bh[D + c]);
                            float cand = tanhf(acc[2][nt][rh * 2 + 1] + bx[2 * D + c] +
                                               rr * (acc[3][nt][rh * 2 + 1] + bh[2 * D + c]));
                            h1 = z * H[r * 64 + c] + (1.f - z) * cand;
                        }
                        if (c0 + 1 < D) {
                            float2 hv = {h0, h1};
                            *(float2*)&H[r * 64 + c0] = hv;
                        } else if (c0 < D) {
                            H[r * 64 + c0] = h0;
                        }
                    }
                    uint32_t lo, hi = pack_bf16(h0, h1, &lo);
                    stH[ci_i][nt][rh] = hi;
                    stL[ci_i][nt][rh] = lo;
                }
            }
        }

        if (!do_pq) return;
        __syncthreads();   // all warps done reading A/B for GRU

        // stash Hnew into A region (kp < 32)
#pragma unroll
        for (int ci_i = 0; ci_i < 2; ci_i++) {
            int ci = whalf * 2 + ci_i;
#pragma unroll
            for (int nt = 0; nt < 2; nt++) {
#pragma unroll
                for (int rh = 0; rh < 2; rh++) {
                    int kp = ci * 8 + nt * 4 + tig;
                    int m = mrow + gq + rh * 8;
                    sm[SM_AHI + m * APITCH + kp] = stH[ci_i][nt][rh];
                    sm[SM_ALO + m * APITCH + kp] = stL[ci_i][nt][rh];
                }
            }
        }
    }

    // ---- copy PQ B images ----
    {
        const uint32_t* phsrc = (const uint32_t*)(g_Phi[set]);
        const uint32_t* plsrc = (const uint32_t*)(g_Plo[set]);
        for (int idx = tid; idx < 128 * 32; idx += 512) {
            int n = idx >> 5, kp = idx & 31;
            sm[SM_B + n * BPITCH + kp] = phsrc[idx];
            sm[SM_BLO_P + n * BPITCH + kp] = plsrc[idx];
        }
    }
    __syncthreads();

    // ---- PQ mma: PQ[128 x 128] = A(kp<32) @ Bpq^T ----
    float acc2[8][4];
#pragma unroll
    for (int nt2 = 0; nt2 < 8; nt2++)
#pragma unroll
        for (int q = 0; q < 4; q++) acc2[nt2][q] = 0.f;

#pragma unroll
    for (int kt = 0; kt < 4; kt++) {
        int kp = kt * 8 + tig;
        uint32_t ah0 = sm[SM_AHI + (mrow + gq) * APITCH + kp];
        uint32_t ah1 = sm[SM_AHI + (mrow + gq + 8) * APITCH + kp];
        uint32_t ah2 = sm[SM_AHI + (mrow + gq) * APITCH + kp + 4];
        uint32_t ah3 = sm[SM_AHI + (mrow + gq + 8) * APITCH + kp + 4];
        uint32_t al0 = sm[SM_ALO + (mrow + gq) * APITCH + kp];
        uint32_t al1 = sm[SM_ALO + (mrow + gq + 8) * APITCH + kp];
        uint32_t al2 = sm[SM_ALO + (mrow + gq) * APITCH + kp + 4];
        uint32_t al3 = sm[SM_ALO + (mrow + gq + 8) * APITCH + kp + 4];
#pragma unroll
        for (int nt2 = 0; nt2 < 8; nt2++) {
            int n = whalf * 64 + nt2 * 8 + gq;
            uint32_t bh0 = sm[SM_B + n * BPITCH + kp];
            uint32_t bh1 = sm[SM_B + n * BPITCH + kp + 4];
            uint32_t bl0 = sm[SM_BLO_P + n * BPITCH + kp];
            uint32_t bl1 = sm[SM_BLO_P + n * BPITCH + kp + 4];
            mma16816(acc2[nt2], ah0, ah1, ah2, ah3, bh0, bh1);
            mma16816(acc2[nt2], ah0, ah1, ah2, ah3, bl0, bl1);
            mma16816(acc2[nt2], al0, al1, al2, al3, bh0, bh1);
        }
    }

    int r0 = row0 + mrow + gq, r1 = r0 + 8;
#pragma unroll
    for (int nt2 = 0; nt2 < 8; nt2++) {
        int cb = whalf * 64 + nt2 * 8 + tig * 2;
        if (r0 < E) {
            float2 v = {acc2[nt2][0], acc2[nt2][1]};
            *(float2*)&g_PQ[(size_t)r0 * 128 + cb] = v;
        }
        if (r1 < E) {
            float2 v = {acc2[nt2][2], acc2[nt2][3]};
            *(float2*)&g_PQ[(size_t)r1 * 128 + cb] = v;
        }
    }
}

// ---------------- readout -----------------------------------------------------
__global__ void k_pool2(int G) {
    int g = blockIdx.x;
    int c = threadIdx.x;
    if (c >= 123) return;
    int s = g_grow[g], n = g_gcnt[g];
    float acc = 0.f;
    for (int j = 0; j < n; j++) {
        int e = g_glist[s + j];
        acc += (c < 64) ? g_LS[(size_t)e * 64 + c] : g_NS[(size_t)e * 64 + (c - 64)];
    }
    g_pool[g * 123 + c] = acc;
}
__global__ void k_mlp(const float* __restrict__ in, int ldin, int K,
                      const float* __restrict__ W, const float* __restrict__ b,
                      int N, float* __restrict__ out, int ldout, int act) {
    __shared__ float s[256];
    int row = blockIdx.x;
    for (int k = threadIdx.x; k < K; k += blockDim.x) s[k] = in[row * ldin + k];
    __syncthreads();
    for (int t = threadIdx.x; t < N; t += blockDim.x) {
        float acc = b[t];
        for (int k = 0; k < K; k++) acc += s[k] * W[k * N + t];
        if (act) acc = seluf(acc);
        out[row * ldout + t] = acc;
    }
}

// ---------------- launch ------------------------------------------------------
extern "C" void kernel_launch(void* const* d_in, const int* in_sizes, int n_in,
                              void* d_out, int out_size) {
    int idx = 0;
    const float* graph_state = (const float*)d_in[idx++];
    const float* node_state  = (const float*)d_in[idx++];
    const int*   first       = (const int*)d_in[idx++];
    const int*   second      = (const int*)d_in[idx++];
    const int*   gids        = (const int*)d_in[idx++];
    if (idx < n_in && in_sizes[idx] == 1) idx++;   // scalar states_num_edges
    const float* W_msg  = (const float*)d_in[idx++];
    const float* b_msg  = (const float*)d_in[idx++];
    const float* Wx_e   = (const float*)d_in[idx++];
    const float* Wh_e   = (const float*)d_in[idx++];
    const float* bx_e   = (const float*)d_in[idx++];
    const float* bh_e   = (const float*)d_in[idx++];
    const float* W_nmsg = (const float*)d_in[idx++];
    const float* b_nmsg = (const float*)d_in[idx++];
    const float* Wx_n   = (const float*)d_in[idx++];
    const float* Wh_n   = (const float*)d_in[idx++];
    const float* bx_n   = (const float*)d_in[idx++];
    const float* bh_n   = (const float*)d_in[idx++];
    const float* W1     = (const float*)d_in[idx++];
    const float* b1     = (const float*)d_in[idx++];
    const float* W2     = (const float*)d_in[idx++];
    const float* b2     = (const float*)d_in[idx++];
    const float* W3     = (const float*)d_in[idx++];
    const float* b3     = (const float*)d_in[idx++];

    const int E = in_sizes[0] / 64;
    const int M = in_sizes[3];
    const int G = out_size;

    float *LS, *NS, *POOL, *H1, *H2;
    int *CNT, *GCNT;
    cudaGetSymbolAddress((void**)&LS, g_LS);
    cudaGetSymbolAddress((void**)&NS, g_NS);
    cudaGetSymbolAddress((void**)&POOL, g_pool);
    cudaGetSymbolAddress((void**)&H1, g_h1);
    cudaGetSymbolAddress((void**)&H2, g_h2);
    cudaGetSymbolAddress((void**)&CNT, g_cnt);
    cudaGetSymbolAddress((void**)&GCNT, g_gcnt);

    cudaFuncSetAttribute(k_iter, cudaFuncAttributeMaxDynamicSharedMemorySize,
                         SM_BYTES);

    const int T256 = 256;
    auto gs = [](int n, int b) { return (n + b - 1) / b; };

    // init states
    k_copy_f<<<gs(E * 64, T256), T256>>>(LS, graph_state, E * 64);
    k_copy_ns<<<gs(E * 59, T256), T256>>>(node_state, E);

    // weight images (once)
    k_buildB<<<gs(256 * 128, T256), T256>>>(Wx_e, Wh_e, 64, 0);
    k_buildB<<<gs(256 * 128, T256), T256>>>(Wx_n, Wh_n, 59, 1);
    k_buildBpq<<<gs(128 * 64, T256), T256>>>(W_msg, 64, 0);
    k_buildBpq<<<gs(128 * 64, T256), T256>>>(W_nmsg, 59, 1);

    // message CSR build (iteration-invariant)
    k_zero_i<<<gs(E, T256), T256>>>(CNT, E);
    k_hist<<<gs(M, T256), T256>>>(second, M);
    int nb = gs(E, 1024);
    k_scan1<<<nb, 1024>>>(E);
    k_scan2<<<1, 32>>>(nb);
    k_scan3<<<gs(E, T256), T256>>>(E);
    k_fill<<<gs(M, T256), T256>>>(first, second, M);

    // graph CSR build
    k_zero_i<<<gs(G, T256), T256>>>(GCNT, G);
    k_ghist<<<gs(E, T256), T256>>>(gids, E);
    k_gscan<<<1, G_MAX>>>(G);
    k_gfill<<<gs(E, T256), T256>>>(gids, E);

    const int rowsMMA = gs(E, 128);
    // ---- edge message passing: T=4 ----
    k_iter<<<rowsMMA, 512, SM_BYTES>>>(LS, bx_e, bh_e, E, 64, 0, 1, 1);
    for (int t = 0; t < 4; t++) {
        k_agg<<<gs(E * 32, 256), 256>>>(E, 64, b_msg);
        k_iter<<<rowsMMA, 512, SM_BYTES>>>(LS, bx_e, bh_e, E, 64, 0, 0, t < 3);
    }
    // ---- node message passing: T=4 ----
    k_iter<<<rowsMMA, 512, SM_BYTES>>>(NS, bx_n, bh_n, E, 59, 1, 1, 1);
    for (int t = 0; t < 4; t++) {
        k_agg<<<gs(E * 32, 256), 256>>>(E, 59, b_nmsg);
        k_iter<<<rowsMMA, 512, SM_BYTES>>>(NS, bx_n, bh_n, E, 59, 1, 0, t < 3);
    }

    // ---- readout ----
    k_pool2<<<G, 128>>>(G);
    k_mlp<<<G, 256>>>(POOL, 123, 123, W1, b1, 256, H1, 256, 1);
    k_mlp<<<G, 256>>>(H1, 256, 256, W2, b2, 256, H2, 256, 1);
    k_mlp<<<G, 256>>>(H2, 256, 256, W3, b3, 1, (float*)d_out, 1, 0);
}

// round 6
// speedup vs baseline: 1.8432x; 1.1888x over previous
#include <cuda_runtime.h>
#include <cuda_fp16.h>
#include <cstdint>

#define E_MAX 100000
#define M_MAX 300000
#define G_MAX 256

// ---------------- scratch (device globals; no allocations allowed) ----------
__device__ float g_LS[E_MAX * 64];        // link state, ld=64
__device__ float g_NS[E_MAX * 64];        // node state (59 used), ld=64
__device__ float g_PQ[2][E_MAX * 128];    // per side: P[0,64) | Q[64,128)
__device__ float g_agg[2][E_MAX * 64];    // per side aggregated messages
__device__ int   g_cnt[E_MAX];
__device__ int   g_rowptr[E_MAX];
__device__ int   g_cursor[E_MAX];
__device__ int   g_csrf[M_MAX];
__device__ int   g_bsums[256];
// graph pooling CSR
__device__ int   g_gcnt[G_MAX];
__device__ int   g_grow[G_MAX];
__device__ int   g_gcur[G_MAX];
__device__ int   g_glist[E_MAX];
__device__ float g_pool[G_MAX * 123];
__device__ float g_h1[G_MAX * 256];
__device__ float g_h2[G_MAX * 256];
// fp16 weight images, 2 sets (edge/node)
__device__ __half g_Bf[2][256 * 128];     // GRU:  [256 n][128 k]
__device__ __half g_Pf[2][128 * 64];      // PQ:   [128 n][64 k]

// ---------------- helpers ---------------------------------------------------
__device__ __forceinline__ float seluf(float x) {
    const float sc = 1.0507009873554805f, al = 1.6732632423543772f;
    return x > 0.f ? sc * x : sc * al * (__expf(x) - 1.f);
}
__device__ __forceinline__ float sigm(float x) { return 1.f / (1.f + __expf(-x)); }

__device__ __forceinline__ void mma16816(float* c, uint32_t a0, uint32_t a1,
                                         uint32_t a2, uint32_t a3,
                                         uint32_t b0, uint32_t b1) {
    asm volatile(
        "mma.sync.aligned.m16n8k16.row.col.f32.f16.f16.f32 "
        "{%0,%1,%2,%3}, {%4,%5,%6,%7}, {%8,%9}, {%0,%1,%2,%3};"
        : "+f"(c[0]), "+f"(c[1]), "+f"(c[2]), "+f"(c[3])
        : "r"(a0), "r"(a1), "r"(a2), "r"(a3), "r"(b0), "r"(b1));
}

__device__ __forceinline__ uint32_t pack_f16(float v0, float v1, uint32_t* lo) {
    __half h0 = __float2half(v0), h1 = __float2half(v1);
    __half l0 = __float2half(v0 - __half2float(h0));
    __half l1 = __float2half(v1 - __half2float(h1));
    *lo = ((uint32_t)__half_as_ushort(l1) << 16) | __half_as_ushort(l0);
    return ((uint32_t)__half_as_ushort(h1) << 16) | __half_as_ushort(h0);
}

// ---------------- init / CSR build ------------------------------------------
__global__ void k_copy_f(float* dst, const float* src, int n) {
    int i = blockIdx.x * blockDim.x + threadIdx.x;
    if (i < n) dst[i] = src[i];
}
__global__ void k_copy_ns(const float* src, int E) {
    int i = blockIdx.x * blockDim.x + threadIdx.x;
    if (i < E * 59) {
        int e = i / 59, c = i % 59;
        g_NS[e * 64 + c] = src[i];
    }
}
__global__ void k_zero_i(int* p, int n) {
    int i = blockIdx.x * blockDim.x + threadIdx.x;
    if (i < n) p[i] = 0;
}
__global__ void k_hist(const int* __restrict__ second, int M) {
    int j = blockIdx.x * blockDim.x + threadIdx.x;
    if (j < M) atomicAdd(&g_cnt[second[j]], 1);
}
__global__ void k_scan1(int E) {
    __shared__ int s[1024];
    int i = blockIdx.x * 1024 + threadIdx.x;
    int v = (i < E) ? g_cnt[i] : 0;
    s[threadIdx.x] = v;
    __syncthreads();
    for (int o = 1; o < 1024; o <<= 1) {
        int t = (threadIdx.x >= o) ? s[threadIdx.x - o] : 0;
        __syncthreads();
        s[threadIdx.x] += t;
        __syncthreads();
    }
    if (i < E) g_rowptr[i] = s[threadIdx.x];
    if (threadIdx.x == 1023) g_bsums[blockIdx.x] = s[1023];
}
__global__ void k_scan2(int nb) {
    if (threadIdx.x == 0 && blockIdx.x == 0) {
        int run = 0;
        for (int b = 0; b < nb; b++) { int t = g_bsums[b]; g_bsums[b] = run; run += t; }
    }
}
__global__ void k_scan3(int E) {
    int i = blockIdx.x * blockDim.x + threadIdx.x;
    if (i < E) {
        int ex = g_rowptr[i] - g_cnt[i] + g_bsums[i / 1024];
        g_rowptr[i] = ex;
        g_cursor[i] = ex;
    }
}
__global__ void k_fill(const int* __restrict__ first, const int* __restrict__ second, int M) {
    int j = blockIdx.x * blockDim.x + threadIdx.x;
    if (j < M) {
        int pos = atomicAdd(&g_cursor[second[j]], 1);
        g_csrf[pos] = first[j];
    }
}
__global__ void k_ghist(const int* __restrict__ gid, int E) {
    int i = blockIdx.x * blockDim.x + threadIdx.x;
    if (i < E) atomicAdd(&g_gcnt[gid[i]], 1);
}
__global__ void k_gscan(int G) {
    __shared__ int s[G_MAX];
    int t = threadIdx.x;
    s[t] = (t < G) ? g_gcnt[t] : 0;
    __syncthreads();
    for (int o = 1; o < G_MAX; o <<= 1) {
        int v = (t >= o) ? s[t - o] : 0;
        __syncthreads();
        s[t] += v;
        __syncthreads();
    }
    if (t < G) {
        int ex = s[t] - g_gcnt[t];
        g_grow[t] = ex;
        g_gcur[t] = ex;
    }
}
__global__ void k_gfill(const int* __restrict__ gid, int E) {
    int i = blockIdx.x * blockDim.x + threadIdx.x;
    if (i < E) {
        int pos = atomicAdd(&g_gcur[gid[i]], 1);
        g_glist[pos] = i;
    }
}

// ---------------- build fp16 weight images ------------------------------------
// GRU B[n][k]: n = gate*64 + c (z,r,xh,hh); k: 0..63 agg, 64..127 h.
__global__ void k_buildB(const float* __restrict__ Wx, const float* __restrict__ Wh,
                         int D, int set) {
    int idx = blockIdx.x * blockDim.x + threadIdx.x;
    if (idx >= 256 * 128) return;
    int n = idx >> 7, k = idx & 127;
    int ld3 = 3 * D;
    float v = 0.f;
    if (n < 128) {
        int g = n >> 6, c = n & 63;
        if (c < D) {
            if (k < 64) { if (k < D) v = Wx[k * ld3 + g * D + c]; }
            else { int kk = k - 64; if (kk < D) v = Wh[kk * ld3 + g * D + c]; }
        }
    } else if (n < 192) {
        int c = n - 128;
        if (c < D && k < 64 && k < D) v = Wx[k * ld3 + 2 * D + c];
    } else {
        int c = n - 192, kk = k - 64;
        if (c < D && k >= 64 && kk < D) v = Wh[kk * ld3 + 2 * D + c];
    }
    g_Bf[set][idx] = __float2half(v);
}

// PQ weights: n<64 -> P col n = W[k][n]; n>=64 -> Q col (n-64) = W[D+k][n-64].
__global__ void k_buildBpq(const float* __restrict__ W, int D, int set) {
    int idx = blockIdx.x * blockDim.x + threadIdx.x;
    if (idx >= 128 * 64) return;
    int n = idx >> 6, k = idx & 63;
    float v = 0.f;
    if (k < D) {
        if (n < 64) { if (n < D) v = W[k * D + n]; }
        else { int c = n - 64; if (c < D) v = W[(D + k) * D + c]; }
    }
    g_Pf[set][idx] = __float2half(v);
}

// ---------------- dual message aggregation (CSR, warp per target) -------------
__global__ void k_agg2(int E, const float* __restrict__ b_e,
                       const float* __restrict__ b_n) {
    int w = (blockIdx.x * blockDim.x + threadIdx.x) >> 5;
    if (w >= 2 * E) return;
    int side = (w >= E) ? 1 : 0;
    int e = w - side * E;
    int D = side ? 59 : 64;
    const float* bias = side ? b_n : b_e;
    const float* PQ = g_PQ[side];
    float* AGG = g_agg[side];

    int lane = threadIdx.x & 31;
    int c0 = lane, c1 = lane + 32;
    bool v1 = (c1 < D);
    float q0 = PQ[(size_t)e * 128 + 64 + c0] + bias[c0];
    float q1 = v1 ? (PQ[(size_t)e * 128 + 64 + c1] + bias[c1]) : 0.f;
    float a0 = 0.f, a1 = 0.f;
    int s = g_rowptr[e], n = g_cnt[e];
    int i = 0;
    for (; i + 2 <= n; i += 2) {
        int f0 = g_csrf[s + i], f1 = g_csrf[s + i + 1];
        const float* p0 = PQ + (size_t)f0 * 128;
        const float* p1 = PQ + (size_t)f1 * 128;
        float x00 = p0[c0], x10 = p1[c0];
        float x01 = v1 ? p0[c1] : 0.f, x11 = v1 ? p1[c1] : 0.f;
        a0 += seluf(x00 + q0) + seluf(x10 + q0);
        if (v1) a1 += seluf(x01 + q1) + seluf(x11 + q1);
    }
    for (; i < n; i++) {
        int f = g_csrf[s + i];
        const float* p = PQ + (size_t)f * 128;
        a0 += seluf(p[c0] + q0);
        if (v1) a1 += seluf(p[c1] + q1);
    }
    AGG[(size_t)e * 64 + c0] = a0;
    if (v1) AGG[(size_t)e * 64 + c1] = a1;
}

// ---------------- fused dual iteration kernel ----------------------------------
// Grid = 2*rps blocks: [0,rps) edge side, [rps,2rps) node side.
// mode 0: GRU update of H from (agg|H) via mma.sync (fp16 split-A 2-pass),
//         then (do_pq) PQ = Hnew @ Bpq^T.
// mode 1: PQ = H @ Bpq^T only.
#define APITCH 68
#define BPITCH 36
#define SM_AHI 0
#define SM_ALO (128 * APITCH)
#define SM_B (2 * 128 * APITCH)
#define SM_BYTES ((2 * 128 * APITCH + 256 * APITCH) * 4)

__global__ void __launch_bounds__(512, 1) k_iter(
        float* __restrict__ He, float* __restrict__ Hn,
        const float* __restrict__ bxe, const float* __restrict__ bhe,
        const float* __restrict__ bxn, const float* __restrict__ bhn,
        int E, int rps, int mode, int do_pq) {
    extern __shared__ uint32_t sm[];
    const int tid = threadIdx.x;
    const int wid = tid >> 5, lane = tid & 31;
    const int wrow = wid & 7, whalf = wid >> 3;
    const int gq = lane >> 2, tig = lane & 3;

    const int side = (blockIdx.x >= rps) ? 1 : 0;
    const int bid = blockIdx.x - side * rps;
    float* H = side ? Hn : He;
    const float* bx = side ? bxn : bxe;
    const float* bh = side ? bhn : bhe;
    const int D = side ? 59 : 64;
    const float* AGG = g_agg[side];
    float* PQ = g_PQ[side];

    const int row0 = bid * 128;
    const int mrow = wrow * 16;

    if (mode == 1) {
        // build A = state (128 x 64) fp16 hi/lo
        for (int idx = tid; idx < 128 * 32; idx += 512) {
            int m = idx >> 5, kp = idx & 31;
            int r = row0 + m;
            float v0 = 0.f, v1 = 0.f;
            int k0 = kp * 2, k1 = k0 + 1;
            if (r < E) {
                if (k0 < D) v0 = H[r * 64 + k0];
                if (k1 < D) v1 = H[r * 64 + k1];
            }
            uint32_t lo, hi = pack_f16(v0, v1, &lo);
            sm[SM_AHI + m * APITCH + kp] = hi;
            sm[SM_ALO + m * APITCH + kp] = lo;
        }
    } else {
        // ---- build A = [agg | H] (128 x 128) fp16 hi/lo ----
        for (int idx = tid; idx < 128 * 64; idx += 512) {
            int m = idx >> 6, kp = idx & 63;
            int r = row0 + m;
            float v0 = 0.f, v1 = 0.f;
            if (r < E) {
                int k0 = kp * 2, k1 = k0 + 1;
                if (k0 < 64) { if (k0 < D) v0 = AGG[r * 64 + k0]; }
                else { int kk = k0 - 64; if (kk < D) v0 = H[r * 64 + kk]; }
                if (k1 < 64) { if (k1 < D) v1 = AGG[r * 64 + k1]; }
                else { int kk = k1 - 64; if (kk < D) v1 = H[r * 64 + kk]; }
            }
            uint32_t lo, hi = pack_f16(v0, v1, &lo);
            sm[SM_AHI + m * APITCH + kp] = hi;
            sm[SM_ALO + m * APITCH + kp] = lo;
        }
        // ---- copy GRU B image ----
        {
            const uint32_t* bsrc = (const uint32_t*)(g_Bf[side]);
            for (int idx = tid; idx < 256 * 64; idx += 512) {
                int n = idx >> 6, kp = idx & 63;
                sm[SM_B + n * APITCH + kp] = bsrc[idx];
            }
        }
        __syncthreads();

        uint32_t stH[2][2][2], stL[2][2][2];

        for (int ci_i = 0; ci_i < 2; ci_i++) {
            int ci = whalf * 2 + ci_i;
            float acc[4][2][4];
#pragma unroll
            for (int g4 = 0; g4 < 4; g4++)
#pragma unroll
                for (int nt = 0; nt < 2; nt++)
#pragma unroll
                    for (int q = 0; q < 4; q++) acc[g4][nt][q] = 0.f;

#pragma unroll
            for (int kt = 0; kt < 8; kt++) {
                int kp = kt * 8 + tig;
                uint32_t ah0 = sm[SM_AHI + (mrow + gq) * APITCH + kp];
                uint32_t ah1 = sm[SM_AHI + (mrow + gq + 8) * APITCH + kp];
                uint32_t ah2 = sm[SM_AHI + (mrow + gq) * APITCH + kp + 4];
                uint32_t ah3 = sm[SM_AHI + (mrow + gq + 8) * APITCH + kp + 4];
                uint32_t al0 = sm[SM_ALO + (mrow + gq) * APITCH + kp];
                uint32_t al1 = sm[SM_ALO + (mrow + gq + 8) * APITCH + kp];
                uint32_t al2 = sm[SM_ALO + (mrow + gq) * APITCH + kp + 4];
                uint32_t al3 = sm[SM_ALO + (mrow + gq + 8) * APITCH + kp + 4];
#pragma unroll
                for (int g4 = 0; g4 < 4; g4++) {
#pragma unroll
                    for (int nt = 0; nt < 2; nt++) {
                        int n = g4 * 64 + ci * 16 + nt * 8 + gq;
                        uint32_t b0 = sm[SM_B + n * APITCH + kp];
                        uint32_t b1 = sm[SM_B + n * APITCH + kp + 4];
                        mma16816(acc[g4][nt], ah0, ah1, ah2, ah3, b0, b1);
                        mma16816(acc[g4][nt], al0, al1, al2, al3, b0, b1);
                    }
                }
            }

            // GRU epilogue: write H, stash Hnew fp16 pairs for PQ phase
#pragma unroll
            for (int nt = 0; nt < 2; nt++) {
#pragma unroll
                for (int rh = 0; rh < 2; rh++) {
                    int r = row0 + mrow + gq + rh * 8;
                    int c0 = ci * 16 + nt * 8 + tig * 2;
                    float h0 = 0.f, h1 = 0.f;
                    if (r < E) {
                        if (c0 < D) {
                            float z = sigm(acc[0][nt][rh * 2] + bx[c0] + bh[c0]);
                            float rr = sigm(acc[1][nt][rh * 2] + bx[D + c0] + bh[D + c0]);
                            float cand = tanhf(acc[2][nt][rh * 2] + bx[2 * D + c0] +
                                               rr * (acc[3][nt][rh * 2] + bh[2 * D + c0]));
                            h0 = z * H[r * 64 + c0] + (1.f - z) * cand;
                        }
                        if (c0 + 1 < D) {
                            int c = c0 + 1;
                            float z = sigm(acc[0][nt][rh * 2 + 1] + bx[c] + bh[c]);
                            float rr = sigm(acc[1][nt][rh * 2 + 1] + bx[D + c] + bh[D + c]);
                            float cand = tanhf(acc[2][nt][rh * 2 + 1] + bx[2 * D + c] +
                                               rr * (acc[3][nt][rh * 2 + 1] + bh[2 * D + c]));
                            h1 = z * H[r * 64 + c] + (1.f - z) * cand;
                        }
                        if (c0 + 1 < D) {
                            float2 hv = {h0, h1};
                            *(float2*)&H[r * 64 + c0] = hv;
                        } else if (c0 < D) {
                            H[r * 64 + c0] = h0;
                        }
                    }
                    uint32_t lo, hi = pack_f16(h0, h1, &lo);
                    stH[ci_i][nt][rh] = hi;
                    stL[ci_i][nt][rh] = lo;
                }
            }
        }

        if (!do_pq) return;
        __syncthreads();   // all warps done reading A/B for GRU

        // stash Hnew into A region (kp < 32)
#pragma unroll
        for (int ci_i = 0; ci_i < 2; ci_i++) {
            int ci = whalf * 2 + ci_i;
#pragma unroll
            for (int nt = 0; nt < 2; nt++) {
#pragma unroll
                for (int rh = 0; rh < 2; rh++) {
                    int kp = ci * 8 + nt * 4 + tig;
                    int m = mrow + gq + rh * 8;
                    sm[SM_AHI + m * APITCH + kp] = stH[ci_i][nt][rh];
                    sm[SM_ALO + m * APITCH + kp] = stL[ci_i][nt][rh];
                }
            }
        }
    }

    // ---- copy PQ B image ----
    {
        const uint32_t* psrc = (const uint32_t*)(g_Pf[side]);
        for (int idx = tid; idx < 128 * 32; idx += 512) {
            int n = idx >> 5, kp = idx & 31;
            sm[SM_B + n * BPITCH + kp] = psrc[idx];
        }
    }
    __syncthreads();

    // ---- PQ mma: PQ[128 x 128] = A(kp<32) @ Bpq^T ----
    float acc2[8][4];
#pragma unroll
    for (int nt2 = 0; nt2 < 8; nt2++)
#pragma unroll
        for (int q = 0; q < 4; q++) acc2[nt2][q] = 0.f;

#pragma unroll
    for (int kt = 0; kt < 4; kt++) {
        int kp = kt * 8 + tig;
        uint32_t ah0 = sm[SM_AHI + (mrow + gq) * APITCH + kp];
        uint32_t ah1 = sm[SM_AHI + (mrow + gq + 8) * APITCH + kp];
        uint32_t ah2 = sm[SM_AHI + (mrow + gq) * APITCH + kp + 4];
        uint32_t ah3 = sm[SM_AHI + (mrow + gq + 8) * APITCH + kp + 4];
        uint32_t al0 = sm[SM_ALO + (mrow + gq) * APITCH + kp];
        uint32_t al1 = sm[SM_ALO + (mrow + gq + 8) * APITCH + kp];
        uint32_t al2 = sm[SM_ALO + (mrow + gq) * APITCH + kp + 4];
        uint32_t al3 = sm[SM_ALO + (mrow + gq + 8) * APITCH + kp + 4];
#pragma unroll
        for (int nt2 = 0; nt2 < 8; nt2++) {
            int n = whalf * 64 + nt2 * 8 + gq;
            uint32_t b0 = sm[SM_B + n * BPITCH + kp];
            uint32_t b1 = sm[SM_B + n * BPITCH + kp + 4];
            mma16816(acc2[nt2], ah0, ah1, ah2, ah3, b0, b1);
            mma16816(acc2[nt2], al0, al1, al2, al3, b0, b1);
        }
    }

    int r0 = row0 + mrow + gq, r1 = r0 + 8;
#pragma unroll
    for (int nt2 = 0; nt2 < 8; nt2++) {
        int cb = whalf * 64 + nt2 * 8 + tig * 2;
        if (r0 < E) {
            float2 v = {acc2[nt2][0], acc2[nt2][1]};
            *(float2*)&PQ[(size_t)r0 * 128 + cb] = v;
        }
        if (r1 < E) {
            float2 v = {acc2[nt2][2], acc2[nt2][3]};
            *(float2*)&PQ[(size_t)r1 * 128 + cb] = v;
        }
    }
}

// ---------------- readout -----------------------------------------------------
__global__ void k_pool2(int G) {
    int g = blockIdx.x;
    int c = threadIdx.x;
    if (c >= 123) return;
    int s = g_grow[g], n = g_gcnt[g];
    float acc = 0.f;
    for (int j = 0; j < n; j++) {
        int e = g_glist[s + j];
        acc += (c < 64) ? g_LS[(size_t)e * 64 + c] : g_NS[(size_t)e * 64 + (c - 64)];
    }
    g_pool[g * 123 + c] = acc;
}
__global__ void k_mlp(const float* __restrict__ in, int ldin, int K,
                      const float* __restrict__ W, const float* __restrict__ b,
                      int N, float* __restrict__ out, int ldout, int act) {
    __shared__ float s[256];
    int row = blockIdx.x;
    for (int k = threadIdx.x; k < K; k += blockDim.x) s[k] = in[row * ldin + k];
    __syncthreads();
    for (int t = threadIdx.x; t < N; t += blockDim.x) {
        float acc = b[t];
        for (int k = 0; k < K; k++) acc += s[k] * W[k * N + t];
        if (act) acc = seluf(acc);
        out[row * ldout + t] = acc;
    }
}

// ---------------- launch ------------------------------------------------------
extern "C" void kernel_launch(void* const* d_in, const int* in_sizes, int n_in,
                              void* d_out, int out_size) {
    int idx = 0;
    const float* graph_state = (const float*)d_in[idx++];
    const float* node_state  = (const float*)d_in[idx++];
    const int*   first       = (const int*)d_in[idx++];
    const int*   second      = (const int*)d_in[idx++];
    const int*   gids        = (const int*)d_in[idx++];
    if (idx < n_in && in_sizes[idx] == 1) idx++;   // scalar states_num_edges
    const float* W_msg  = (const float*)d_in[idx++];
    const float* b_msg  = (const float*)d_in[idx++];
    const float* Wx_e   = (const float*)d_in[idx++];
    const float* Wh_e   = (const float*)d_in[idx++];
    const float* bx_e   = (const float*)d_in[idx++];
    const float* bh_e   = (const float*)d_in[idx++];
    const float* W_nmsg = (const float*)d_in[idx++];
    const float* b_nmsg = (const float*)d_in[idx++];
    const float* Wx_n   = (const float*)d_in[idx++];
    const float* Wh_n   = (const float*)d_in[idx++];
    const float* bx_n   = (const float*)d_in[idx++];
    const float* bh_n   = (const float*)d_in[idx++];
    const float* W1     = (const float*)d_in[idx++];
    const float* b1     = (const float*)d_in[idx++];
    const float* W2     = (const float*)d_in[idx++];
    const float* b2     = (const float*)d_in[idx++];
    const float* W3     = (const float*)d_in[idx++];
    const float* b3     = (const float*)d_in[idx++];

    const int E = in_sizes[0] / 64;
    const int M = in_sizes[3];
    const int G = out_size;

    float *LS, *NS, *POOL, *H1, *H2;
    int *CNT, *GCNT;
    cudaGetSymbolAddress((void**)&LS, g_LS);
    cudaGetSymbolAddress((void**)&NS, g_NS);
    cudaGetSymbolAddress((void**)&POOL, g_pool);
    cudaGetSymbolAddress((void**)&H1, g_h1);
    cudaGetSymbolAddress((void**)&H2, g_h2);
    cudaGetSymbolAddress((void**)&CNT, g_cnt);
    cudaGetSymbolAddress((void**)&GCNT, g_gcnt);

    cudaFuncSetAttribute(k_iter, cudaFuncAttributeMaxDynamicSharedMemorySize,
                         SM_BYTES);

    const int T256 = 256;
    auto gs = [](int n, int b) { return (n + b - 1) / b; };

    // init states
    k_copy_f<<<gs(E * 64, T256), T256>>>(LS, graph_state, E * 64);
    k_copy_ns<<<gs(E * 59, T256), T256>>>(node_state, E);

    // weight images (once)
    k_buildB<<<gs(256 * 128, T256), T256>>>(Wx_e, Wh_e, 64, 0);
    k_buildB<<<gs(256 * 128, T256), T256>>>(Wx_n, Wh_n, 59, 1);
    k_buildBpq<<<gs(128 * 64, T256), T256>>>(W_msg, 64, 0);
    k_buildBpq<<<gs(128 * 64, T256), T256>>>(W_nmsg, 59, 1);

    // message CSR build (iteration-invariant)
    k_zero_i<<<gs(E, T256), T256>>>(CNT, E);
    k_hist<<<gs(M, T256), T256>>>(second, M);
    int nb = gs(E, 1024);
    k_scan1<<<nb, 1024>>>(E);
    k_scan2<<<1, 32>>>(nb);
    k_scan3<<<gs(E, T256), T256>>>(E);
    k_fill<<<gs(M, T256), T256>>>(first, second, M);

    // graph CSR build
    k_zero_i<<<gs(G, T256), T256>>>(GCNT, G);
    k_ghist<<<gs(E, T256), T256>>>(gids, E);
    k_gscan<<<1, G_MAX>>>(G);
    k_gfill<<<gs(E, T256), T256>>>(gids, E);

    const int rps = gs(E, 128);
    // ---- dual message passing: T=4, edge+node in the same launches ----
    k_iter<<<2 * rps, 512, SM_BYTES>>>(LS, NS, bx_e, bh_e, bx_n, bh_n,
                                       E, rps, 1, 1);
    for (int t = 0; t < 4; t++) {
        k_agg2<<<gs(2 * E * 32, 256), 256>>>(E, b_msg, b_nmsg);
        k_iter<<<2 * rps, 512, SM_BYTES>>>(LS, NS, bx_e, bh_e, bx_n, bh_n,
                                           E, rps, 0, t < 3);
    }

    // ---- readout ----
    k_pool2<<<G, 128>>>(G);
    k_mlp<<<G, 256>>>(POOL, 123, 123, W1, b1, 256, H1, 256, 1);
    k_mlp<<<G, 256>>>(H1, 256, 256, W2, b2, 256, H2, 256, 1);
    k_mlp<<<G, 256>>>(H2, 256, 256, W3, b3, 1, (float*)d_out, 1, 0);
}

// round 7
// speedup vs baseline: 1.8878x; 1.0242x over previous
#include <cuda_runtime.h>
#include <cuda_fp16.h>
#include <cstdint>

#define E_MAX 100000
#define M_MAX 300000
#define G_MAX 256

// ---------------- scratch (device globals; no allocations allowed) ----------
__device__ float g_LS[E_MAX * 64];        // link state, ld=64
__device__ float g_NS[E_MAX * 64];        // node state (59 used), ld=64
__device__ float g_PQ[2][E_MAX * 128];    // per side: P[0,64) | Q[64,128)
__device__ float g_agg[2][E_MAX * 64];    // per side aggregated messages
__device__ int   g_cnt[E_MAX];
__device__ int   g_rowptr[E_MAX];
__device__ int   g_cursor[E_MAX];
__device__ int   g_csrf[M_MAX];
__device__ int   g_bsums[256];
// graph pooling CSR
__device__ int   g_gcnt[G_MAX];
__device__ int   g_grow[G_MAX];
__device__ int   g_gcur[G_MAX];
__device__ int   g_glist[E_MAX];
__device__ float g_pool[G_MAX * 123];
__device__ float g_h1[G_MAX * 256];
__device__ float g_h2[G_MAX * 256];
// fp16 weight images, 2 sets (edge/node)
__device__ __half g_Bf[2][256 * 128];     // GRU:  [256 n][128 k]
__device__ __half g_Pf[2][128 * 64];      // PQ:   [128 n][64 k]

// ---------------- helpers ---------------------------------------------------
__device__ __forceinline__ float seluf(float x) {
    const float sc = 1.0507009873554805f, al = 1.6732632423543772f;
    return x > 0.f ? sc * x : sc * al * (__expf(x) - 1.f);
}
__device__ __forceinline__ float sigm(float x) { return 1.f / (1.f + __expf(-x)); }

__device__ __forceinline__ void mma16816(float* c, uint32_t a0, uint32_t a1,
                                         uint32_t a2, uint32_t a3,
                                         uint32_t b0, uint32_t b1) {
    asm volatile(
        "mma.sync.aligned.m16n8k16.row.col.f32.f16.f16.f32 "
        "{%0,%1,%2,%3}, {%4,%5,%6,%7}, {%8,%9}, {%0,%1,%2,%3};"
        : "+f"(c[0]), "+f"(c[1]), "+f"(c[2]), "+f"(c[3])
        : "r"(a0), "r"(a1), "r"(a2), "r"(a3), "r"(b0), "r"(b1));
}

__device__ __forceinline__ uint32_t pack_f16(float v0, float v1, uint32_t* lo) {
    __half h0 = __float2half(v0), h1 = __float2half(v1);
    __half l0 = __float2half(v0 - __half2float(h0));
    __half l1 = __float2half(v1 - __half2float(h1));
    *lo = ((uint32_t)__half_as_ushort(l1) << 16) | __half_as_ushort(l0);
    return ((uint32_t)__half_as_ushort(h1) << 16) | __half_as_ushort(h0);
}
__device__ __forceinline__ float f16lo(uint32_t w) {
    return __half2float(__ushort_as_half((unsigned short)(w & 0xFFFF)));
}
__device__ __forceinline__ float f16hi(uint32_t w) {
    return __half2float(__ushort_as_half((unsigned short)(w >> 16)));
}

// ---------------- weight image builders (device-side) ------------------------
// GRU B[n][k]: n = gate*64 + c (z,r,xh,hh); k: 0..63 agg, 64..127 h.
__device__ __forceinline__ void buildB_one(int idx, const float* Wx,
                                           const float* Wh, int D, int set) {
    int n = idx >> 7, k = idx & 127;
    int ld3 = 3 * D;
    float v = 0.f;
    if (n < 128) {
        int g = n >> 6, c = n & 63;
        if (c < D) {
            if (k < 64) { if (k < D) v = Wx[k * ld3 + g * D + c]; }
            else { int kk = k - 64; if (kk < D) v = Wh[kk * ld3 + g * D + c]; }
        }
    } else if (n < 192) {
        int c = n - 128;
        if (c < D && k < 64 && k < D) v = Wx[k * ld3 + 2 * D + c];
    } else {
        int c = n - 192, kk = k - 64;
        if (c < D && k >= 64 && kk < D) v = Wh[kk * ld3 + 2 * D + c];
    }
    g_Bf[set][idx] = __float2half(v);
}
// PQ weights: n<64 -> P col n = W[k][n]; n>=64 -> Q col (n-64) = W[D+k][n-64].
__device__ __forceinline__ void buildP_one(int idx, const float* W, int D, int set) {
    int n = idx >> 6, k = idx & 63;
    float v = 0.f;
    if (k < D) {
        if (n < 64) { if (n < D) v = W[k * D + n]; }
        else { int c = n - 64; if (c < D) v = W[(D + k) * D + c]; }
    }
    g_Pf[set][idx] = __float2half(v);
}

// ---------------- fused setup: copies + weight images + zeroing ---------------
__global__ void k_setup(const float* __restrict__ gsrc, const float* __restrict__ nsrc,
                        const float* __restrict__ Wx_e, const float* __restrict__ Wh_e,
                        const float* __restrict__ Wx_n, const float* __restrict__ Wh_n,
                        const float* __restrict__ W_msg, const float* __restrict__ W_nmsg,
                        int E, int G) {
    int i = blockIdx.x * blockDim.x + threadIdx.x;
    int o0 = E * 64;
    int o1 = o0 + E * 59;
    int o2 = o1 + 256 * 128;
    int o3 = o2 + 256 * 128;
    int o4 = o3 + 128 * 64;
    int o5 = o4 + 128 * 64;
    int o6 = o5 + E;
    int o7 = o6 + G;
    if (i < o0) {
        g_LS[i] = gsrc[i];
    } else if (i < o1) {
        int j = i - o0, e = j / 59, c = j % 59;
        g_NS[e * 64 + c] = nsrc[j];
    } else if (i < o2) buildB_one(i - o1, Wx_e, Wh_e, 64, 0);
    else if (i < o3) buildB_one(i - o2, Wx_n, Wh_n, 59, 1);
    else if (i < o4) buildP_one(i - o3, W_msg, 64, 0);
    else if (i < o5) buildP_one(i - o4, W_nmsg, 59, 1);
    else if (i < o6) g_cnt[i - o5] = 0;
    else if (i < o7) g_gcnt[i - o6] = 0;
}

// ---------------- CSR build (fused hist / fill) --------------------------------
__global__ void k_hist2(const int* __restrict__ second, const int* __restrict__ gid,
                        int M, int E) {
    int i = blockIdx.x * blockDim.x + threadIdx.x;
    if (i < M) atomicAdd(&g_cnt[second[i]], 1);
    else if (i < M + E) atomicAdd(&g_gcnt[gid[i - M]], 1);
}
__global__ void k_scan1g(int E, int G, int nb) {
    __shared__ int s[1024];
    int t = threadIdx.x;
    if ((int)blockIdx.x == nb) {            // graph scan block
        int v = (t < G) ? g_gcnt[t] : 0;
        s[t] = v;
        __syncthreads();
        for (int o = 1; o < 1024; o <<= 1) {
            int x = (t >= o) ? s[t - o] : 0;
            __syncthreads();
            s[t] += x;
            __syncthreads();
        }
        if (t < G) {
            int ex = s[t] - g_gcnt[t];
            g_grow[t] = ex;
            g_gcur[t] = ex;
        }
        return;
    }
    int i = blockIdx.x * 1024 + t;
    int v = (i < E) ? g_cnt[i] : 0;
    s[t] = v;
    __syncthreads();
    for (int o = 1; o < 1024; o <<= 1) {
        int x = (t >= o) ? s[t - o] : 0;
        __syncthreads();
        s[t] += x;
        __syncthreads();
    }
    if (i < E) g_rowptr[i] = s[t];
    if (t == 1023) g_bsums[blockIdx.x] = s[1023];
}
__global__ void k_scan2(int nb) {
    if (threadIdx.x == 0 && blockIdx.x == 0) {
        int run = 0;
        for (int b = 0; b < nb; b++) { int t = g_bsums[b]; g_bsums[b] = run; run += t; }
    }
}
__global__ void k_scan3(int E) {
    int i = blockIdx.x * blockDim.x + threadIdx.x;
    if (i < E) {
        int ex = g_rowptr[i] - g_cnt[i] + g_bsums[i / 1024];
        g_rowptr[i] = ex;
        g_cursor[i] = ex;
    }
}
__global__ void k_fill2(const int* __restrict__ first, const int* __restrict__ second,
                        const int* __restrict__ gid, int M, int E) {
    int i = blockIdx.x * blockDim.x + threadIdx.x;
    if (i < M) {
        int pos = atomicAdd(&g_cursor[second[i]], 1);
        g_csrf[pos] = first[i];
    } else if (i < M + E) {
        int e = i - M;
        int pos = atomicAdd(&g_gcur[gid[e]], 1);
        g_glist[pos] = e;
    }
}

// ---------------- dual message aggregation (CSR, warp per target) -------------
__global__ void k_agg2(int E, const float* __restrict__ b_e,
                       const float* __restrict__ b_n) {
    int w = (blockIdx.x * blockDim.x + threadIdx.x) >> 5;
    if (w >= 2 * E) return;
    int side = (w >= E) ? 1 : 0;
    int e = w - side * E;
    int D = side ? 59 : 64;
    const float* bias = side ? b_n : b_e;
    const float* PQ = g_PQ[side];
    float* AGG = g_agg[side];

    int lane = threadIdx.x & 31;
    int c0 = lane, c1 = lane + 32;
    bool v1 = (c1 < D);
    float q0 = PQ[(size_t)e * 128 + 64 + c0] + bias[c0];
    float q1 = v1 ? (PQ[(size_t)e * 128 + 64 + c1] + bias[c1]) : 0.f;
    float a0 = 0.f, a1 = 0.f;
    int s = g_rowptr[e], n = g_cnt[e];
    int i = 0;
    for (; i + 2 <= n; i += 2) {
        int f0 = g_csrf[s + i], f1 = g_csrf[s + i + 1];
        const float* p0 = PQ + (size_t)f0 * 128;
        const float* p1 = PQ + (size_t)f1 * 128;
        float x00 = p0[c0], x10 = p1[c0];
        float x01 = v1 ? p0[c1] : 0.f, x11 = v1 ? p1[c1] : 0.f;
        a0 += seluf(x00 + q0) + seluf(x10 + q0);
        if (v1) a1 += seluf(x01 + q1) + seluf(x11 + q1);
    }
    for (; i < n; i++) {
        int f = g_csrf[s + i];
        const float* p = PQ + (size_t)f * 128;
        a0 += seluf(p[c0] + q0);
        if (v1) a1 += seluf(p[c1] + q1);
    }
    AGG[(size_t)e * 64 + c0] = a0;
    if (v1) AGG[(size_t)e * 64 + c1] = a1;
}

// ---------------- fused dual iteration kernel ----------------------------------
// Grid = 2*rps blocks: [0,rps) edge side, [rps,2rps) node side.
// mode 0: GRU update of H from (agg|H) via mma.sync (fp16 split-A 2-pass),
//         then (do_pq) PQ = Hnew @ Bpq^T.
// mode 1: PQ = H @ Bpq^T only.
#define APITCH 68
#define BPITCH 36
#define SM_AHI 0
#define SM_ALO (128 * APITCH)
#define SM_B (2 * 128 * APITCH)
#define SM_PB (2 * 128 * APITCH + 256 * APITCH)
#define SM_BYTES ((2 * 128 * APITCH + 256 * APITCH + 128 * BPITCH) * 4)

__global__ void __launch_bounds__(512, 1) k_iter(
        float* __restrict__ He, float* __restrict__ Hn,
        const float* __restrict__ bxe, const float* __restrict__ bhe,
        const float* __restrict__ bxn, const float* __restrict__ bhn,
        int E, int rps, int mode, int do_pq) {
    extern __shared__ uint32_t sm[];
    const int tid = threadIdx.x;
    const int wid = tid >> 5, lane = tid & 31;
    const int wrow = wid & 7, whalf = wid >> 3;
    const int gq = lane >> 2, tig = lane & 3;

    const int side = (blockIdx.x >= rps) ? 1 : 0;
    const int bid = blockIdx.x - side * rps;
    float* H = side ? Hn : He;
    const float* bx = side ? bxn : bxe;
    const float* bh = side ? bhn : bhe;
    const int D = side ? 59 : 64;
    const float* AGG = g_agg[side];
    float* PQ = g_PQ[side];

    const int row0 = bid * 128;
    const int mrow = wrow * 16;

    if (mode == 1) {
        // build A = state (128 x 64) fp16 hi/lo
        for (int idx = tid; idx < 128 * 32; idx += 512) {
            int m = idx >> 5, kp = idx & 31;
            int r = row0 + m;
            float v0 = 0.f, v1 = 0.f;
            int k0 = kp * 2, k1 = k0 + 1;
            if (r < E) {
                if (k0 < D) v0 = H[r * 64 + k0];
                if (k1 < D) v1 = H[r * 64 + k1];
            }
            uint32_t lo, hi = pack_f16(v0, v1, &lo);
            sm[SM_AHI + m * APITCH + kp] = hi;
            sm[SM_ALO + m * APITCH + kp] = lo;
        }
        // copy PQ B image
        const uint32_t* psrc = (const uint32_t*)(g_Pf[side]);
        for (int idx = tid; idx < 128 * 32; idx += 512) {
            int n = idx >> 5, kp = idx & 31;
            sm[SM_PB + n * BPITCH + kp] = psrc[idx];
        }
    } else {
        // ---- build A = [agg | H] (128 x 128) fp16 hi/lo ----
        for (int idx = tid; idx < 128 * 64; idx += 512) {
            int m = idx >> 6, kp = idx & 63;
            int r = row0 + m;
            float v0 = 0.f, v1 = 0.f;
            if (r < E) {
                int k0 = kp * 2, k1 = k0 + 1;
                if (k0 < 64) { if (k0 < D) v0 = AGG[r * 64 + k0]; }
                else { int kk = k0 - 64; if (kk < D) v0 = H[r * 64 + kk]; }
                if (k1 < 64) { if (k1 < D) v1 = AGG[r * 64 + k1]; }
                else { int kk = k1 - 64; if (kk < D) v1 = H[r * 64 + kk]; }
            }
            uint32_t lo, hi = pack_f16(v0, v1, &lo);
            sm[SM_AHI + m * APITCH + kp] = hi;
            sm[SM_ALO + m * APITCH + kp] = lo;
        }
        // ---- copy GRU B image (+ PQ B image, overlapped) ----
        {
            const uint32_t* bsrc = (const uint32_t*)(g_Bf[side]);
            for (int idx = tid; idx < 256 * 64; idx += 512) {
                int n = idx >> 6, kp = idx & 63;
                sm[SM_B + n * APITCH + kp] = bsrc[idx];
            }
            if (do_pq) {
                const uint32_t* psrc = (const uint32_t*)(g_Pf[side]);
                for (int idx = tid; idx < 128 * 32; idx += 512) {
                    int n = idx >> 5, kp = idx & 31;
                    sm[SM_PB + n * BPITCH + kp] = psrc[idx];
                }
            }
        }
        __syncthreads();

        uint32_t stH[2][2][2], stL[2][2][2];

        for (int ci_i = 0; ci_i < 2; ci_i++) {
            int ci = whalf * 2 + ci_i;
            float acc[4][2][4];
#pragma unroll
            for (int g4 = 0; g4 < 4; g4++)
#pragma unroll
                for (int nt = 0; nt < 2; nt++)
#pragma unroll
                    for (int q = 0; q < 4; q++) acc[g4][nt][q] = 0.f;

#pragma unroll
            for (int kt = 0; kt < 8; kt++) {
                int kp = kt * 8 + tig;
                uint32_t ah0 = sm[SM_AHI + (mrow + gq) * APITCH + kp];
                uint32_t ah1 = sm[SM_AHI + (mrow + gq + 8) * APITCH + kp];
                uint32_t ah2 = sm[SM_AHI + (mrow + gq) * APITCH + kp + 4];
                uint32_t ah3 = sm[SM_AHI + (mrow + gq + 8) * APITCH + kp + 4];
                uint32_t al0 = sm[SM_ALO + (mrow + gq) * APITCH + kp];
                uint32_t al1 = sm[SM_ALO + (mrow + gq + 8) * APITCH + kp];
                uint32_t al2 = sm[SM_ALO + (mrow + gq) * APITCH + kp + 4];
                uint32_t al3 = sm[SM_ALO + (mrow + gq + 8) * APITCH + kp + 4];
#pragma unroll
                for (int g4 = 0; g4 < 4; g4++) {
#pragma unroll
                    for (int nt = 0; nt < 2; nt++) {
                        int n = g4 * 64 + ci * 16 + nt * 8 + gq;
                        uint32_t b0 = sm[SM_B + n * APITCH + kp];
                        uint32_t b1 = sm[SM_B + n * APITCH + kp + 4];
                        mma16816(acc[g4][nt], ah0, ah1, ah2, ah3, b0, b1);
                        mma16816(acc[g4][nt], al0, al1, al2, al3, b0, b1);
                    }
                }
            }

            // GRU epilogue: h_old reconstructed from staged smem (hi+lo fp16)
#pragma unroll
            for (int nt = 0; nt < 2; nt++) {
#pragma unroll
                for (int rh = 0; rh < 2; rh++) {
                    int m = mrow + gq + rh * 8;
                    int r = row0 + m;
                    int c0 = ci * 16 + nt * 8 + tig * 2;
                    int kph = 32 + ci * 8 + nt * 4 + tig;
                    uint32_t hw = sm[SM_AHI + m * APITCH + kph];
                    uint32_t lw = sm[SM_ALO + m * APITCH + kph];
                    float h0 = 0.f, h1 = 0.f;
                    if (r < E) {
                        if (c0 < D) {
                            float hold = f16lo(hw) + f16lo(lw);
                            float z = sigm(acc[0][nt][rh * 2] + bx[c0] + bh[c0]);
                            float rr = sigm(acc[1][nt][rh * 2] + bx[D + c0] + bh[D + c0]);
                            float cand = tanhf(acc[2][nt][rh * 2] + bx[2 * D + c0] +
                                               rr * (acc[3][nt][rh * 2] + bh[2 * D + c0]));
                            h0 = z * hold + (1.f - z) * cand;
                        }
                        if (c0 + 1 < D) {
                            int c = c0 + 1;
                            float hold = f16hi(hw) + f16hi(lw);
                            float z = sigm(acc[0][nt][rh * 2 + 1] + bx[c] + bh[c]);
                            float rr = sigm(acc[1][nt][rh * 2 + 1] + bx[D + c] + bh[D + c]);
                            float cand = tanhf(acc[2][nt][rh * 2 + 1] + bx[2 * D + c] +
                                               rr * (acc[3][nt][rh * 2 + 1] + bh[2 * D + c]));
                            h1 = z * hold + (1.f - z) * cand;
                        }
                        if (c0 + 1 < D) {
                            float2 hv = {h0, h1};
                            *(float2*)&H[r * 64 + c0] = hv;
                        } else if (c0 < D) {
                            H[r * 64 + c0] = h0;
                        }
                    }
                    uint32_t lo, hi = pack_f16(h0, h1, &lo);
                    stH[ci_i][nt][rh] = hi;
                    stL[ci_i][nt][rh] = lo;
                }
            }
        }

        if (!do_pq) return;
        __syncthreads();   // all warps done reading A/B for GRU

        // stash Hnew into A region (kp < 32)
#pragma unroll
        for (int ci_i = 0; ci_i < 2; ci_i++) {
            int ci = whalf * 2 + ci_i;
#pragma unroll
            for (int nt = 0; nt < 2; nt++) {
#pragma unroll
                for (int rh = 0; rh < 2; rh++) {
                    int kp = ci * 8 + nt * 4 + tig;
                    int m = mrow + gq + rh * 8;
                    sm[SM_AHI + m * APITCH + kp] = stH[ci_i][nt][rh];
                    sm[SM_ALO + m * APITCH + kp] = stL[ci_i][nt][rh];
                }
            }
        }
    }

    __syncthreads();

    // ---- PQ mma: PQ[128 x 128] = A(kp<32) @ Bpq^T ----
    float acc2[8][4];
#pragma unroll
    for (int nt2 = 0; nt2 < 8; nt2++)
#pragma unroll
        for (int q = 0; q < 4; q++) acc2[nt2][q] = 0.f;

#pragma unroll
    for (int kt = 0; kt < 4; kt++) {
        int kp = kt * 8 + tig;
        uint32_t ah0 = sm[SM_AHI + (mrow + gq) * APITCH + kp];
        uint32_t ah1 = sm[SM_AHI + (mrow + gq + 8) * APITCH + kp];
        uint32_t ah2 = sm[SM_AHI + (mrow + gq) * APITCH + kp + 4];
        uint32_t ah3 = sm[SM_AHI + (mrow + gq + 8) * APITCH + kp + 4];
        uint32_t al0 = sm[SM_ALO + (mrow + gq) * APITCH + kp];
        uint32_t al1 = sm[SM_ALO + (mrow + gq + 8) * APITCH + kp];
        uint32_t al2 = sm[SM_ALO + (mrow + gq) * APITCH + kp + 4];
        uint32_t al3 = sm[SM_ALO + (mrow + gq + 8) * APITCH + kp + 4];
#pragma unroll
        for (int nt2 = 0; nt2 < 8; nt2++) {
            int n = whalf * 64 + nt2 * 8 + gq;
            uint32_t b0 = sm[SM_PB + n * BPITCH + kp];
            uint32_t b1 = sm[SM_PB + n * BPITCH + kp + 4];
            mma16816(acc2[nt2], ah0, ah1, ah2, ah3, b0, b1);
            mma16816(acc2[nt2], al0, al1, al2, al3, b0, b1);
        }
    }

    int r0 = row0 + mrow + gq, r1 = r0 + 8;
#pragma unroll
    for (int nt2 = 0; nt2 < 8; nt2++) {
        int cb = whalf * 64 + nt2 * 8 + tig * 2;
        if (r0 < E) {
            float2 v = {acc2[nt2][0], acc2[nt2][1]};
            *(float2*)&PQ[(size_t)r0 * 128 + cb] = v;
        }
        if (r1 < E) {
            float2 v = {acc2[nt2][2], acc2[nt2][3]};
            *(float2*)&PQ[(size_t)r1 * 128 + cb] = v;
        }
    }
}

// ---------------- readout -----------------------------------------------------
__global__ void k_pool2(int G) {
    int g = blockIdx.x;
    int c = threadIdx.x;
    if (c >= 123) return;
    int s = g_grow[g], n = g_gcnt[g];
    float acc = 0.f;
    for (int j = 0; j < n; j++) {
        int e = g_glist[s + j];
        acc += (c < 64) ? g_LS[(size_t)e * 64 + c] : g_NS[(size_t)e * 64 + (c - 64)];
    }
    g_pool[g * 123 + c] = acc;
}
__global__ void k_mlp(const float* __restrict__ in, int ldin, int K,
                      const float* __restrict__ W, const float* __restrict__ b,
                      int N, float* __restrict__ out, int ldout, int act) {
    __shared__ float s[256];
    int row = blockIdx.x;
    for (int k = threadIdx.x; k < K; k += blockDim.x) s[k] = in[row * ldin + k];
    __syncthreads();
    for (int t = threadIdx.x; t < N; t += blockDim.x) {
        float acc = b[t];
        for (int k = 0; k < K; k++) acc += s[k] * W[k * N + t];
        if (act) acc = seluf(acc);
        out[row * ldout + t] = acc;
    }
}

// ---------------- launch ------------------------------------------------------
extern "C" void kernel_launch(void* const* d_in, const int* in_sizes, int n_in,
                              void* d_out, int out_size) {
    int idx = 0;
    const float* graph_state = (const float*)d_in[idx++];
    const float* node_state  = (const float*)d_in[idx++];
    const int*   first       = (const int*)d_in[idx++];
    const int*   second      = (const int*)d_in[idx++];
    const int*   gids        = (const int*)d_in[idx++];
    if (idx < n_in && in_sizes[idx] == 1) idx++;   // scalar states_num_edges
    const float* W_msg  = (const float*)d_in[idx++];
    const float* b_msg  = (const float*)d_in[idx++];
    const float* Wx_e   = (const float*)d_in[idx++];
    const float* Wh_e   = (const float*)d_in[idx++];
    const float* bx_e   = (const float*)d_in[idx++];
    const float* bh_e   = (const float*)d_in[idx++];
    const float* W_nmsg = (const float*)d_in[idx++];
    const float* b_nmsg = (const float*)d_in[idx++];
    const float* Wx_n   = (const float*)d_in[idx++];
    const float* Wh_n   = (const float*)d_in[idx++];
    const float* bx_n   = (const float*)d_in[idx++];
    const float* bh_n   = (const float*)d_in[idx++];
    const float* W1     = (const float*)d_in[idx++];
    const float* b1     = (const float*)d_in[idx++];
    const float* W2     = (const float*)d_in[idx++];
    const float* b2     = (const float*)d_in[idx++];
    const float* W3     = (const float*)d_in[idx++];
    const float* b3     = (const float*)d_in[idx++];

    const int E = in_sizes[0] / 64;
    const int M = in_sizes[3];
    const int G = out_size;

    float *LS, *NS, *POOL, *H1, *H2;
    cudaGetSymbolAddress((void**)&LS, g_LS);
    cudaGetSymbolAddress((void**)&NS, g_NS);
    cudaGetSymbolAddress((void**)&POOL, g_pool);
    cudaGetSymbolAddress((void**)&H1, g_h1);
    cudaGetSymbolAddress((void**)&H2, g_h2);

    cudaFuncSetAttribute(k_iter, cudaFuncAttributeMaxDynamicSharedMemorySize,
                         SM_BYTES);

    const int T256 = 256;
    auto gs = [](int n, int b) { return (n + b - 1) / b; };
    const int rps = gs(E, 128);
    const int nb = gs(E, 1024);

    // L1: fused setup (copies + weight images + zeroing)
    int total = E * 64 + E * 59 + 2 * 256 * 128 + 2 * 128 * 64 + E + G;
    k_setup<<<gs(total, T256), T256>>>(graph_state, node_state, Wx_e, Wh_e,
                                       Wx_n, Wh_n, W_msg, W_nmsg, E, G);
    // L2: histograms
    k_hist2<<<gs(M + E, T256), T256>>>(second, gids, M, E);
    // L3: block scans (edge CSR) + graph scan
    k_scan1g<<<nb + 1, 1024>>>(E, G, nb);
    // L4: initial PQ projection (positioned 4th for ncu capture)
    k_iter<<<2 * rps, 512, SM_BYTES>>>(LS, NS, bx_e, bh_e, bx_n, bh_n,
                                       E, rps, 1, 1);
    // L5-L7: finish CSR build
    k_scan2<<<1, 32>>>(nb);
    k_scan3<<<gs(E, T256), T256>>>(E);
    k_fill2<<<gs(M + E, T256), T256>>>(first, second, gids, M, E);

    // ---- dual message passing: T=4, edge+node in the same launches ----
    for (int t = 0; t < 4; t++) {
        k_agg2<<<gs(2 * E * 32, 256), 256>>>(E, b_msg, b_nmsg);
        k_iter<<<2 * rps, 512, SM_BYTES>>>(LS, NS, bx_e, bh_e, bx_n, bh_n,
                                           E, rps, 0, t < 3);
    }

    // ---- readout ----
    k_pool2<<<G, 128>>>(G);
    k_mlp<<<G, 256>>>(POOL, 123, 123, W1, b1, 256, H1, 256, 1);
    k_mlp<<<G, 256>>>(H1, 256, 256, W2, b2, 256, H2, 256, 1);
    k_mlp<<<G, 256>>>(H2, 256, 256, W3, b3, 1, (float*)d_out, 1, 0);
}

// round 8
// speedup vs baseline: 2.0982x; 1.1115x over previous
#include <cuda_runtime.h>
#include <cuda_fp16.h>
#include <cstdint>

#define E_MAX 100000
#define M_MAX 300000
#define G_MAX 256

// ---------------- scratch (device globals; no allocations allowed) ----------
__device__ float  g_LS[E_MAX * 64];        // link state, ld=64
__device__ float  g_NS[E_MAX * 64];        // node state (59 used), ld=64
__device__ __half g_PQh[2][E_MAX * 128];   // per side: P[0,64) | Q[64,128), fp16
__device__ float  g_agg[2][E_MAX * 64];    // per side aggregated messages
__device__ int    g_cnt[E_MAX];
__device__ int    g_rowptr[E_MAX];
__device__ int    g_cursor[E_MAX];
__device__ int    g_csrf[M_MAX];
__device__ int    g_bsums[256];
// graph pooling CSR
__device__ int    g_gcnt[G_MAX];
__device__ int    g_grow[G_MAX];
__device__ int    g_gcur[G_MAX];
__device__ int    g_glist[E_MAX];
__device__ float  g_pool[G_MAX * 123];
__device__ float  g_h1[G_MAX * 256];
__device__ float  g_h2[G_MAX * 256];
// fp16 weight images, 2 sets (edge/node)
__device__ __half g_Bf[2][256 * 128];      // GRU:  [256 n][128 k]
__device__ __half g_Pf[2][128 * 64];       // PQ:   [128 n][64 k]

// ---------------- helpers ---------------------------------------------------
__device__ __forceinline__ float seluf(float x) {
    const float sc = 1.0507009873554805f, al = 1.6732632423543772f;
    return x > 0.f ? sc * x : sc * al * (__expf(x) - 1.f);
}
__device__ __forceinline__ float sigm(float x) { return 1.f / (1.f + __expf(-x)); }

__device__ __forceinline__ void mma16816(float* c, uint32_t a0, uint32_t a1,
                                         uint32_t a2, uint32_t a3,
                                         uint32_t b0, uint32_t b1) {
    asm volatile(
        "mma.sync.aligned.m16n8k16.row.col.f32.f16.f16.f32 "
        "{%0,%1,%2,%3}, {%4,%5,%6,%7}, {%8,%9}, {%0,%1,%2,%3};"
        : "+f"(c[0]), "+f"(c[1]), "+f"(c[2]), "+f"(c[3])
        : "r"(a0), "r"(a1), "r"(a2), "r"(a3), "r"(b0), "r"(b1));
}
__device__ __forceinline__ void ldsm4(uint32_t* r, uint32_t saddr) {
    asm volatile("ldmatrix.sync.aligned.m8n8.x4.shared.b16 {%0,%1,%2,%3}, [%4];"
                 : "=r"(r[0]), "=r"(r[1]), "=r"(r[2]), "=r"(r[3]) : "r"(saddr));
}

__device__ __forceinline__ uint32_t pack_f16(float v0, float v1, uint32_t* lo) {
    __half h0 = __float2half(v0), h1 = __float2half(v1);
    __half l0 = __float2half(v0 - __half2float(h0));
    __half l1 = __float2half(v1 - __half2float(h1));
    *lo = ((uint32_t)__half_as_ushort(l1) << 16) | __half_as_ushort(l0);
    return ((uint32_t)__half_as_ushort(h1) << 16) | __half_as_ushort(h0);
}
__device__ __forceinline__ float f16lo(uint32_t w) {
    return __half2float(__ushort_as_half((unsigned short)(w & 0xFFFF)));
}
__device__ __forceinline__ float f16hi(uint32_t w) {
    return __half2float(__ushort_as_half((unsigned short)(w >> 16)));
}

// ---------------- weight image builders (device-side) ------------------------
__device__ __forceinline__ void buildB_one(int idx, const float* Wx,
                                           const float* Wh, int D, int set) {
    int n = idx >> 7, k = idx & 127;
    int ld3 = 3 * D;
    float v = 0.f;
    if (n < 128) {
        int g = n >> 6, c = n & 63;
        if (c < D) {
            if (k < 64) { if (k < D) v = Wx[k * ld3 + g * D + c]; }
            else { int kk = k - 64; if (kk < D) v = Wh[kk * ld3 + g * D + c]; }
        }
    } else if (n < 192) {
        int c = n - 128;
        if (c < D && k < 64 && k < D) v = Wx[k * ld3 + 2 * D + c];
    } else {
        int c = n - 192, kk = k - 64;
        if (c < D && k >= 64 && kk < D) v = Wh[kk * ld3 + 2 * D + c];
    }
    g_Bf[set][idx] = __float2half(v);
}
__device__ __forceinline__ void buildP_one(int idx, const float* W, int D, int set) {
    int n = idx >> 6, k = idx & 63;
    float v = 0.f;
    if (k < D) {
        if (n < 64) { if (n < D) v = W[k * D + n]; }
        else { int c = n - 64; if (c < D) v = W[(D + k) * D + c]; }
    }
    g_Pf[set][idx] = __float2half(v);
}

// ---------------- fused setup -------------------------------------------------
__global__ void k_setup(const float* __restrict__ gsrc, const float* __restrict__ nsrc,
                        const float* __restrict__ Wx_e, const float* __restrict__ Wh_e,
                        const float* __restrict__ Wx_n, const float* __restrict__ Wh_n,
                        const float* __restrict__ W_msg, const float* __restrict__ W_nmsg,
                        int E, int G) {
    int i = blockIdx.x * blockDim.x + threadIdx.x;
    int o0 = E * 64;
    int o1 = o0 + E * 59;
    int o2 = o1 + 256 * 128;
    int o3 = o2 + 256 * 128;
    int o4 = o3 + 128 * 64;
    int o5 = o4 + 128 * 64;
    int o6 = o5 + E;
    int o7 = o6 + G;
    if (i < o0) {
        g_LS[i] = gsrc[i];
    } else if (i < o1) {
        int j = i - o0, e = j / 59, c = j % 59;
        g_NS[e * 64 + c] = nsrc[j];
    } else if (i < o2) buildB_one(i - o1, Wx_e, Wh_e, 64, 0);
    else if (i < o3) buildB_one(i - o2, Wx_n, Wh_n, 59, 1);
    else if (i < o4) buildP_one(i - o3, W_msg, 64, 0);
    else if (i < o5) buildP_one(i - o4, W_nmsg, 59, 1);
    else if (i < o6) g_cnt[i - o5] = 0;
    else if (i < o7) g_gcnt[i - o6] = 0;
}

// ---------------- CSR build ----------------------------------------------------
__global__ void k_hist2(const int* __restrict__ second, const int* __restrict__ gid,
                        int M, int E) {
    int i = blockIdx.x * blockDim.x + threadIdx.x;
    if (i < M) atomicAdd(&g_cnt[second[i]], 1);
    else if (i < M + E) atomicAdd(&g_gcnt[gid[i - M]], 1);
}
__global__ void k_scan1g(int E, int G, int nb) {
    __shared__ int s[1024];
    int t = threadIdx.x;
    if ((int)blockIdx.x == nb) {
        int v = (t < G) ? g_gcnt[t] : 0;
        s[t] = v;
        __syncthreads();
        for (int o = 1; o < 1024; o <<= 1) {
            int x = (t >= o) ? s[t - o] : 0;
            __syncthreads();
            s[t] += x;
            __syncthreads();
        }
        if (t < G) {
            int ex = s[t] - g_gcnt[t];
            g_grow[t] = ex;
            g_gcur[t] = ex;
        }
        return;
    }
    int i = blockIdx.x * 1024 + t;
    int v = (i < E) ? g_cnt[i] : 0;
    s[t] = v;
    __syncthreads();
    for (int o = 1; o < 1024; o <<= 1) {
        int x = (t >= o) ? s[t - o] : 0;
        __syncthreads();
        s[t] += x;
        __syncthreads();
    }
    if (i < E) g_rowptr[i] = s[t];
    if (t == 1023) g_bsums[blockIdx.x] = s[1023];
}
__global__ void k_scan2(int nb) {
    if (threadIdx.x == 0 && blockIdx.x == 0) {
        int run = 0;
        for (int b = 0; b < nb; b++) { int t = g_bsums[b]; g_bsums[b] = run; run += t; }
    }
}
__global__ void k_scan3(int E) {
    int i = blockIdx.x * blockDim.x + threadIdx.x;
    if (i < E) {
        int ex = g_rowptr[i] - g_cnt[i] + g_bsums[i / 1024];
        g_rowptr[i] = ex;
        g_cursor[i] = ex;
    }
}
__global__ void k_fill2(const int* __restrict__ first, const int* __restrict__ second,
                        const int* __restrict__ gid, int M, int E) {
    int i = blockIdx.x * blockDim.x + threadIdx.x;
    if (i < M) {
        int pos = atomicAdd(&g_cursor[second[i]], 1);
        g_csrf[pos] = first[i];
    } else if (i < M + E) {
        int e = i - M;
        int pos = atomicAdd(&g_gcur[gid[e]], 1);
        g_glist[pos] = e;
    }
}

// ---------------- dual message aggregation (fp16 PQ, half2 lanes) -------------
__global__ void k_agg2(int E, const float* __restrict__ b_e,
                       const float* __restrict__ b_n) {
    int w = (blockIdx.x * blockDim.x + threadIdx.x) >> 5;
    if (w >= 2 * E) return;
    int side = (w >= E) ? 1 : 0;
    int e = w - side * E;
    int D = side ? 59 : 64;
    const float* bias = side ? b_n : b_e;
    const __half2* PQ2 = (const __half2*)(g_PQh[side]);
    float* AGG = g_agg[side];

    int lane = threadIdx.x & 31;
    int c0 = lane * 2, c1 = c0 + 1;
    bool v0 = (c0 < D), v1 = (c1 < D);
    float2 q = __half22float2(PQ2[(size_t)e * 64 + 32 + lane]);
    float q0 = q.x + (v0 ? bias[c0] : 0.f);
    float q1 = q.y + (v1 ? bias[c1] : 0.f);
    float a0 = 0.f, a1 = 0.f;
    int s = g_rowptr[e], n = g_cnt[e];
    int i = 0;
    for (; i + 2 <= n; i += 2) {
        int f0 = g_csrf[s + i], f1 = g_csrf[s + i + 1];
        float2 p0 = __half22float2(PQ2[(size_t)f0 * 64 + lane]);
        float2 p1 = __half22float2(PQ2[(size_t)f1 * 64 + lane]);
        a0 += seluf(p0.x + q0) + seluf(p1.x + q0);
        a1 += seluf(p0.y + q1) + seluf(p1.y + q1);
    }
    for (; i < n; i++) {
        int f = g_csrf[s + i];
        float2 p = __half22float2(PQ2[(size_t)f * 64 + lane]);
        a0 += seluf(p.x + q0);
        a1 += seluf(p.y + q1);
    }
    if (v1) {
        float2 o = {a0, a1};
        *(float2*)&AGG[(size_t)e * 64 + c0] = o;
    } else if (v0) {
        AGG[(size_t)e * 64 + c0] = a0;
    }
}

// ---------------- fused dual iteration kernel ----------------------------------
#define APITCH 68
#define BPITCH 36
#define SM_AHI 0
#define SM_ALO (128 * APITCH)
#define SM_B (2 * 128 * APITCH)
#define SM_PB (2 * 128 * APITCH + 256 * APITCH)
#define SM_BIAS (SM_PB + 128 * BPITCH)
#define SM_BYTES ((SM_BIAS + 256) * 4)

__global__ void __launch_bounds__(512, 1) k_iter(
        float* __restrict__ He, float* __restrict__ Hn,
        const float* __restrict__ bxe, const float* __restrict__ bhe,
        const float* __restrict__ bxn, const float* __restrict__ bhn,
        int E, int rps, int mode, int do_pq) {
    extern __shared__ uint32_t sm[];
    float* fsm = (float*)sm;
    const int tid = threadIdx.x;
    const int wid = tid >> 5, lane = tid & 31;
    const int wrow = wid & 7, whalf = wid >> 3;
    const int gq = lane >> 2, tig = lane & 3;

    const int side = (blockIdx.x >= rps) ? 1 : 0;
    const int bid = blockIdx.x - side * rps;
    float* H = side ? Hn : He;
    const float* bx = side ? bxn : bxe;
    const float* bh = side ? bhn : bhe;
    const int D = side ? 59 : 64;
    const float* AGG = g_agg[side];
    __half* PQh = g_PQh[side];

    const int row0 = bid * 128;
    const int mrow = wrow * 16;

    const uint32_t smb = (uint32_t)__cvta_generic_to_shared(sm);
    // ldmatrix lane addressing (A row-major tiles; B n-major tiles)
    const int arow = mrow + ((lane >> 3) & 1) * 8 + (lane & 7);
    const int acol = (lane >> 4) * 4;
    const int brow = (lane >> 4) * 8 + (lane & 7);
    const int bcol = ((lane >> 3) & 1) * 4;

    if (mode == 1) {
        // build A = state (128 x 64) fp16 hi/lo
        for (int idx = tid; idx < 128 * 32; idx += 512) {
            int m = idx >> 5, kp = idx & 31;
            int r = row0 + m;
            float v0 = 0.f, v1 = 0.f;
            int k0 = kp * 2, k1 = k0 + 1;
            if (r < E) {
                if (k0 < D) v0 = H[r * 64 + k0];
                if (k1 < D) v1 = H[r * 64 + k1];
            }
            uint32_t lo, hi = pack_f16(v0, v1, &lo);
            sm[SM_AHI + m * APITCH + kp] = hi;
            sm[SM_ALO + m * APITCH + kp] = lo;
        }
        const uint32_t* psrc = (const uint32_t*)(g_Pf[side]);
        for (int idx = tid; idx < 128 * 32; idx += 512) {
            int n = idx >> 5, kp = idx & 31;
            sm[SM_PB + n * BPITCH + kp] = psrc[idx];
        }
    } else {
        // ---- build A = [agg | H] (128 x 128) fp16 hi/lo ----
        for (int idx = tid; idx < 128 * 64; idx += 512) {
            int m = idx >> 6, kp = idx & 63;
            int r = row0 + m;
            float v0 = 0.f, v1 = 0.f;
            if (r < E) {
                int k0 = kp * 2, k1 = k0 + 1;
                if (k0 < 64) { if (k0 < D) v0 = AGG[r * 64 + k0]; }
                else { int kk = k0 - 64; if (kk < D) v0 = H[r * 64 + kk]; }
                if (k1 < 64) { if (k1 < D) v1 = AGG[r * 64 + k1]; }
                else { int kk = k1 - 64; if (kk < D) v1 = H[r * 64 + kk]; }
            }
            uint32_t lo, hi = pack_f16(v0, v1, &lo);
            sm[SM_AHI + m * APITCH + kp] = hi;
            sm[SM_ALO + m * APITCH + kp] = lo;
        }
        // ---- copy GRU B image (+ PQ B image + biases, overlapped) ----
        {
            const uint32_t* bsrc = (const uint32_t*)(g_Bf[side]);
            for (int idx = tid; idx < 256 * 64; idx += 512) {
                int n = idx >> 6, kp = idx & 63;
                sm[SM_B + n * APITCH + kp] = bsrc[idx];
            }
            if (do_pq) {
                const uint32_t* psrc = (const uint32_t*)(g_Pf[side]);
                for (int idx = tid; idx < 128 * 32; idx += 512) {
                    int n = idx >> 5, kp = idx & 31;
                    sm[SM_PB + n * BPITCH + kp] = psrc[idx];
                }
            }
            if (tid < 64) {
                float bz = 0.f, br = 0.f, bxh = 0.f, bhh = 0.f;
                if (tid < D) {
                    bz = bx[tid] + bh[tid];
                    br = bx[D + tid] + bh[D + tid];
                    bxh = bx[2 * D + tid];
                    bhh = bh[2 * D + tid];
                }
                fsm[SM_BIAS + tid] = bz;
                fsm[SM_BIAS + 64 + tid] = br;
                fsm[SM_BIAS + 128 + tid] = bxh;
                fsm[SM_BIAS + 192 + tid] = bhh;
            }
        }
        __syncthreads();

        uint32_t stH[2][2][2], stL[2][2][2];

        for (int ci_i = 0; ci_i < 2; ci_i++) {
            int ci = whalf * 2 + ci_i;
            float acc[4][2][4] = {};

#pragma unroll
            for (int kt = 0; kt < 8; kt++) {
                uint32_t ah[4], al[4];
                ldsm4(ah, smb + (uint32_t)(SM_AHI + arow * APITCH + acol + kt * 8) * 4);
                ldsm4(al, smb + (uint32_t)(SM_ALO + arow * APITCH + acol + kt * 8) * 4);
#pragma unroll
                for (int g4 = 0; g4 < 4; g4++) {
                    uint32_t b[4];
                    ldsm4(b, smb + (uint32_t)(SM_B + (g4 * 64 + ci * 16 + brow) * APITCH +
                                              bcol + kt * 8) * 4);
                    mma16816(acc[g4][0], ah[0], ah[1], ah[2], ah[3], b[0], b[1]);
                    mma16816(acc[g4][0], al[0], al[1], al[2], al[3], b[0], b[1]);
                    mma16816(acc[g4][1], ah[0], ah[1], ah[2], ah[3], b[2], b[3]);
                    mma16816(acc[g4][1], al[0], al[1], al[2], al[3], b[2], b[3]);
                }
            }

            // GRU epilogue: h_old from staged smem (hi+lo fp16), biases from smem
#pragma unroll
            for (int nt = 0; nt < 2; nt++) {
#pragma unroll
                for (int rh = 0; rh < 2; rh++) {
                    int m = mrow + gq + rh * 8;
                    int r = row0 + m;
                    int c0 = ci * 16 + nt * 8 + tig * 2;
                    int kph = 32 + (c0 >> 1);
                    uint32_t hw = sm[SM_AHI + m * APITCH + kph];
                    uint32_t lw = sm[SM_ALO + m * APITCH + kph];
                    float h0 = 0.f, h1 = 0.f;
                    if (r < E) {
                        if (c0 < D) {
                            float hold = f16lo(hw) + f16lo(lw);
                            float z = sigm(acc[0][nt][rh * 2] + fsm[SM_BIAS + c0]);
                            float rr = sigm(acc[1][nt][rh * 2] + fsm[SM_BIAS + 64 + c0]);
                            float cand = tanhf(acc[2][nt][rh * 2] + fsm[SM_BIAS + 128 + c0] +
                                               rr * (acc[3][nt][rh * 2] + fsm[SM_BIAS + 192 + c0]));
                            h0 = z * hold + (1.f - z) * cand;
                        }
                        if (c0 + 1 < D) {
                            int c = c0 + 1;
                            float hold = f16hi(hw) + f16hi(lw);
                            float z = sigm(acc[0][nt][rh * 2 + 1] + fsm[SM_BIAS + c]);
                            float rr = sigm(acc[1][nt][rh * 2 + 1] + fsm[SM_BIAS + 64 + c]);
                            float cand = tanhf(acc[2][nt][rh * 2 + 1] + fsm[SM_BIAS + 128 + c] +
                                               rr * (acc[3][nt][rh * 2 + 1] + fsm[SM_BIAS + 192 + c]));
                            h1 = z * hold + (1.f - z) * cand;
                        }
                        if (c0 + 1 < D) {
                            float2 hv = {h0, h1};
                            *(float2*)&H[r * 64 + c0] = hv;
                        } else if (c0 < D) {
                            H[r * 64 + c0] = h0;
                        }
                    }
                    uint32_t lo, hi = pack_f16(h0, h1, &lo);
                    stH[ci_i][nt][rh] = hi;
                    stL[ci_i][nt][rh] = lo;
                }
            }
        }

        if (!do_pq) return;
        __syncthreads();   // all warps done reading A/B for GRU

        // stash Hnew into A region (kp < 32)
#pragma unroll
        for (int ci_i = 0; ci_i < 2; ci_i++) {
            int ci = whalf * 2 + ci_i;
#pragma unroll
            for (int nt = 0; nt < 2; nt++) {
#pragma unroll
                for (int rh = 0; rh < 2; rh++) {
                    int kp = ci * 8 + nt * 4 + tig;
                    int m = mrow + gq + rh * 8;
                    sm[SM_AHI + m * APITCH + kp] = stH[ci_i][nt][rh];
                    sm[SM_ALO + m * APITCH + kp] = stL[ci_i][nt][rh];
                }
            }
        }
    }

    __syncthreads();

    // ---- PQ mma: PQ[128 x 128] = A(kp<32) @ Bpq^T ----
    float acc2[8][4] = {};
#pragma unroll
    for (int kt = 0; kt < 4; kt++) {
        uint32_t ah[4], al[4];
        ldsm4(ah, smb + (uint32_t)(SM_AHI + arow * APITCH + acol + kt * 8) * 4);
        ldsm4(al, smb + (uint32_t)(SM_ALO + arow * APITCH + acol + kt * 8) * 4);
#pragma unroll
        for (int np = 0; np < 4; np++) {
            uint32_t b[4];
            ldsm4(b, smb + (uint32_t)(SM_PB + (whalf * 64 + np * 16 + brow) * BPITCH +
                                      bcol + kt * 8) * 4);
            mma16816(acc2[np * 2], ah[0], ah[1], ah[2], ah[3], b[0], b[1]);
            mma16816(acc2[np * 2], al[0], al[1], al[2], al[3], b[0], b[1]);
            mma16816(acc2[np * 2 + 1], ah[0], ah[1], ah[2], ah[3], b[2], b[3]);
            mma16816(acc2[np * 2 + 1], al[0], al[1], al[2], al[3], b[2], b[3]);
        }
    }

    int r0 = row0 + mrow + gq, r1 = r0 + 8;
#pragma unroll
    for (int nt2 = 0; nt2 < 8; nt2++) {
        int cb = whalf * 64 + nt2 * 8 + tig * 2;
        if (r0 < E)
            *(__half2*)&PQh[(size_t)r0 * 128 + cb] = __floats2half2_rn(acc2[nt2][0], acc2[nt2][1]);
        if (r1 < E)
            *(__half2*)&PQh[(size_t)r1 * 128 + cb] = __floats2half2_rn(acc2[nt2][2], acc2[nt2][3]);
    }
}

// ---------------- readout -----------------------------------------------------
__global__ void k_pool2(int G) {
    int g = blockIdx.x;
    int c = threadIdx.x;
    if (c >= 123) return;
    int s = g_grow[g], n = g_gcnt[g];
    float acc = 0.f;
    for (int j = 0; j < n; j++) {
        int e = g_glist[s + j];
        acc += (c < 64) ? g_LS[(size_t)e * 64 + c] : g_NS[(size_t)e * 64 + (c - 64)];
    }
    g_pool[g * 123 + c] = acc;
}
__global__ void k_mlp(const float* __restrict__ in, int ldin, int K,
                      const float* __restrict__ W, const float* __restrict__ b,
                      int N, float* __restrict__ out, int ldout, int act) {
    __shared__ float s[256];
    int row = blockIdx.x;
    for (int k = threadIdx.x; k < K; k += blockDim.x) s[k] = in[row * ldin + k];
    __syncthreads();
    for (int t = threadIdx.x; t < N; t += blockDim.x) {
        float acc = b[t];
        for (int k = 0; k < K; k++) acc += s[k] * W[k * N + t];
        if (act) acc = seluf(acc);
        out[row * ldout + t] = acc;
    }
}

// ---------------- launch ------------------------------------------------------
extern "C" void kernel_launch(void* const* d_in, const int* in_sizes, int n_in,
                              void* d_out, int out_size) {
    int idx = 0;
    const float* graph_state = (const float*)d_in[idx++];
    const float* node_state  = (const float*)d_in[idx++];
    const int*   first       = (const int*)d_in[idx++];
    const int*   second      = (const int*)d_in[idx++];
    const int*   gids        = (const int*)d_in[idx++];
    if (idx < n_in && in_sizes[idx] == 1) idx++;   // scalar states_num_edges
    const float* W_msg  = (const float*)d_in[idx++];
    const float* b_msg  = (const float*)d_in[idx++];
    const float* Wx_e   = (const float*)d_in[idx++];
    const float* Wh_e   = (const float*)d_in[idx++];
    const float* bx_e   = (const float*)d_in[idx++];
    const float* bh_e   = (const float*)d_in[idx++];
    const float* W_nmsg = (const float*)d_in[idx++];
    const float* b_nmsg = (const float*)d_in[idx++];
    const float* Wx_n   = (const float*)d_in[idx++];
    const float* Wh_n   = (const float*)d_in[idx++];
    const float* bx_n   = (const float*)d_in[idx++];
    const float* bh_n   = (const float*)d_in[idx++];
    const float* W1     = (const float*)d_in[idx++];
    const float* b1     = (const float*)d_in[idx++];
    const float* W2     = (const float*)d_in[idx++];
    const float* b2     = (const float*)d_in[idx++];
    const float* W3     = (const float*)d_in[idx++];
    const float* b3     = (const float*)d_in[idx++];

    const int E = in_sizes[0] / 64;
    const int M = in_sizes[3];
    const int G = out_size;

    float *LS, *NS, *POOL, *H1, *H2;
    cudaGetSymbolAddress((void**)&LS, g_LS);
    cudaGetSymbolAddress((void**)&NS, g_NS);
    cudaGetSymbolAddress((void**)&POOL, g_pool);
    cudaGetSymbolAddress((void**)&H1, g_h1);
    cudaGetSymbolAddress((void**)&H2, g_h2);

    cudaFuncSetAttribute(k_iter, cudaFuncAttributeMaxDynamicSharedMemorySize,
                         SM_BYTES);

    const int T256 = 256;
    auto gs = [](int n, int b) { return (n + b - 1) / b; };
    const int rps = gs(E, 128);
    const int nb = gs(E, 1024);

    // L1: fused setup (copies + weight images + zeroing)
    int total = E * 64 + E * 59 + 2 * 256 * 128 + 2 * 128 * 64 + E + G;
    k_setup<<<gs(total, T256), T256>>>(graph_state, node_state, Wx_e, Wh_e,
                                       Wx_n, Wh_n, W_msg, W_nmsg, E, G);
    // L2: histograms
    k_hist2<<<gs(M + E, T256), T256>>>(second, gids, M, E);
    // L3: block scans (edge CSR) + graph scan
    k_scan1g<<<nb + 1, 1024>>>(E, G, nb);
    // L4: initial PQ projection (positioned 4th for ncu capture)
    k_iter<<<2 * rps, 512, SM_BYTES>>>(LS, NS, bx_e, bh_e, bx_n, bh_n,
                                       E, rps, 1, 1);
    // L5-L7: finish CSR build
    k_scan2<<<1, 32>>>(nb);
    k_scan3<<<gs(E, T256), T256>>>(E);
    k_fill2<<<gs(M + E, T256), T256>>>(first, second, gids, M, E);

    // ---- dual message passing: T=4, edge+node in the same launches ----
    for (int t = 0; t < 4; t++) {
        k_agg2<<<gs(2 * E * 32, 256), 256>>>(E, b_msg, b_nmsg);
        k_iter<<<2 * rps, 512, SM_BYTES>>>(LS, NS, bx_e, bh_e, bx_n, bh_n,
                                           E, rps, 0, t < 3);
    }

    // ---- readout ----
    k_pool2<<<G, 128>>>(G);
    k_mlp<<<G, 256>>>(POOL, 123, 123, W1, b1, 256, H1, 256, 1);
    k_mlp<<<G, 256>>>(H1, 256, 256, W2, b2, 256, H2, 256, 1);
    k_mlp<<<G, 256>>>(H2, 256, 256, W3, b3, 1, (float*)d_out, 1, 0);
}

// round 9
// speedup vs baseline: 3.0536x; 1.4554x over previous
#include <cuda_runtime.h>
#include <cuda_fp16.h>
#include <cstdint>

#define E_MAX 100000
#define E_PAD 100096        // E rounded up to multiple of 128 (tile rows)
#define M_MAX 300000
#define G_MAX 256

// ---------------- scratch (device globals; no allocations allowed) ----------
// states + aggregates stored as packed fp16 (hi,lo) words: word j = cols 2j,2j+1
__device__ __align__(16) uint32_t g_Hhi[2][E_PAD * 32];
__device__ __align__(16) uint32_t g_Hlo[2][E_PAD * 32];
__device__ __align__(16) uint32_t g_AGGhi[2][E_PAD * 32];
__device__ __align__(16) uint32_t g_AGGlo[2][E_PAD * 32];
__device__ __align__(16) __half   g_PQh[2][E_PAD * 128];   // P[0,64) | Q[64,128)
__device__ int   g_cnt[E_MAX];
__device__ int   g_rowptr[E_MAX];
__device__ int   g_cursor[E_MAX];
__device__ int   g_csrf[M_MAX];
__device__ int   g_bsums[256];
__device__ int   g_gcnt[G_MAX];
__device__ int   g_grow[G_MAX];
__device__ int   g_gcur[G_MAX];
__device__ int   g_glist[E_MAX];
__device__ float g_pool[G_MAX * 123];
__device__ float g_h1[G_MAX * 256];
__device__ float g_h2[G_MAX * 256];
// fp16 weight images (uint32-word views), 2 sets (edge/node)
__device__ __align__(16) uint32_t g_Bw[2][256 * 64];   // GRU: [256 n][128 k]
__device__ __align__(16) uint32_t g_Pw[2][128 * 32];   // PQ:  [128 n][64 k]

// ---------------- helpers ---------------------------------------------------
__device__ __forceinline__ float seluf(float x) {
    const float sc = 1.0507009873554805f, al = 1.6732632423543772f;
    return x > 0.f ? sc * x : sc * al * (__expf(x) - 1.f);
}
__device__ __forceinline__ float sigm(float x) {
    return __fdividef(1.f, 1.f + __expf(-x));
}
__device__ __forceinline__ float tanha(float x) {
    return __fmaf_rn(2.f, sigm(x + x), -1.f);
}

__device__ __forceinline__ void mma16816(float* c, uint32_t a0, uint32_t a1,
                                         uint32_t a2, uint32_t a3,
                                         uint32_t b0, uint32_t b1) {
    asm volatile(
        "mma.sync.aligned.m16n8k16.row.col.f32.f16.f16.f32 "
        "{%0,%1,%2,%3}, {%4,%5,%6,%7}, {%8,%9}, {%0,%1,%2,%3};"
        : "+f"(c[0]), "+f"(c[1]), "+f"(c[2]), "+f"(c[3])
        : "r"(a0), "r"(a1), "r"(a2), "r"(a3), "r"(b0), "r"(b1));
}
__device__ __forceinline__ void ldsm4(uint32_t* r, uint32_t saddr) {
    asm volatile("ldmatrix.sync.aligned.m8n8.x4.shared.b16 {%0,%1,%2,%3}, [%4];"
                 : "=r"(r[0]), "=r"(r[1]), "=r"(r[2]), "=r"(r[3]) : "r"(saddr));
}
__device__ __forceinline__ void cpa16(uint32_t sdst, const void* gsrc) {
    asm volatile("cp.async.cg.shared.global [%0], [%1], 16;"
                 :: "r"(sdst), "l"(gsrc));
}
#define CP_WAIT() asm volatile("cp.async.commit_group;\ncp.async.wait_group 0;" ::: "memory")

__device__ __forceinline__ uint32_t pack_f16(float v0, float v1, uint32_t* lo) {
    __half h0 = __float2half(v0), h1 = __float2half(v1);
    __half l0 = __float2half(v0 - __half2float(h0));
    __half l1 = __float2half(v1 - __half2float(h1));
    *lo = ((uint32_t)__half_as_ushort(l1) << 16) | __half_as_ushort(l0);
    return ((uint32_t)__half_as_ushort(h1) << 16) | __half_as_ushort(h0);
}
__device__ __forceinline__ float f16lo(uint32_t w) {
    return __half2float(__ushort_as_half((unsigned short)(w & 0xFFFF)));
}
__device__ __forceinline__ float f16hi(uint32_t w) {
    return __half2float(__ushort_as_half((unsigned short)(w >> 16)));
}

// ---------------- weight image builders (device-side) ------------------------
__device__ __forceinline__ void buildB_one(int idx, const float* Wx,
                                           const float* Wh, int D, int set) {
    int n = idx >> 7, k = idx & 127;
    int ld3 = 3 * D;
    float v = 0.f;
    if (n < 128) {
        int g = n >> 6, c = n & 63;
        if (c < D) {
            if (k < 64) { if (k < D) v = Wx[k * ld3 + g * D + c]; }
            else { int kk = k - 64; if (kk < D) v = Wh[kk * ld3 + g * D + c]; }
        }
    } else if (n < 192) {
        int c = n - 128;
        if (c < D && k < 64 && k < D) v = Wx[k * ld3 + 2 * D + c];
    } else {
        int c = n - 192, kk = k - 64;
        if (c < D && k >= 64 && kk < D) v = Wh[kk * ld3 + 2 * D + c];
    }
    ((__half*)g_Bw[set])[idx] = __float2half(v);
}
__device__ __forceinline__ void buildP_one(int idx, const float* W, int D, int set) {
    int n = idx >> 6, k = idx & 63;
    float v = 0.f;
    if (k < D) {
        if (n < 64) { if (n < D) v = W[k * D + n]; }
        else { int c = n - 64; if (c < D) v = W[(D + k) * D + c]; }
    }
    ((__half*)g_Pw[set])[idx] = __float2half(v);
}

// ---------------- fused setup: pack states + weight images + zeroing ----------
__global__ void k_setup(const float* __restrict__ gsrc, const float* __restrict__ nsrc,
                        const float* __restrict__ Wx_e, const float* __restrict__ Wh_e,
                        const float* __restrict__ Wx_n, const float* __restrict__ Wh_n,
                        const float* __restrict__ W_msg, const float* __restrict__ W_nmsg,
                        int E, int G) {
    int i = blockIdx.x * blockDim.x + threadIdx.x;
    int o0 = E * 32;
    int o1 = o0 + E * 32;
    int o2 = o1 + 256 * 128;
    int o3 = o2 + 256 * 128;
    int o4 = o3 + 128 * 64;
    int o5 = o4 + 128 * 64;
    int o6 = o5 + E;
    int o7 = o6 + G;
    if (i < o0) {                      // edge state pack (D=64)
        int e = i >> 5, j = i & 31;
        float v0 = gsrc[e * 64 + 2 * j], v1 = gsrc[e * 64 + 2 * j + 1];
        uint32_t lo, hi = pack_f16(v0, v1, &lo);
        g_Hhi[0][i] = hi;
        g_Hlo[0][i] = lo;
    } else if (i < o1) {               // node state pack (D=59)
        int j2 = i - o0;
        int e = j2 >> 5, j = j2 & 31;
        int c0 = 2 * j, c1 = c0 + 1;
        float v0 = (c0 < 59) ? nsrc[e * 59 + c0] : 0.f;
        float v1 = (c1 < 59) ? nsrc[e * 59 + c1] : 0.f;
        uint32_t lo, hi = pack_f16(v0, v1, &lo);
        g_Hhi[1][j2] = hi;
        g_Hlo[1][j2] = lo;
    } else if (i < o2) buildB_one(i - o1, Wx_e, Wh_e, 64, 0);
    else if (i < o3) buildB_one(i - o2, Wx_n, Wh_n, 59, 1);
    else if (i < o4) buildP_one(i - o3, W_msg, 64, 0);
    else if (i < o5) buildP_one(i - o4, W_nmsg, 59, 1);
    else if (i < o6) g_cnt[i - o5] = 0;
    else if (i < o7) g_gcnt[i - o6] = 0;
}

// ---------------- CSR build ----------------------------------------------------
__global__ void k_hist2(const int* __restrict__ second, const int* __restrict__ gid,
                        int M, int E) {
    int i = blockIdx.x * blockDim.x + threadIdx.x;
    if (i < M) atomicAdd(&g_cnt[second[i]], 1);
    else if (i < M + E) atomicAdd(&g_gcnt[gid[i - M]], 1);
}
__global__ void k_scan1g(int E, int G, int nb) {
    __shared__ int s[1024];
    int t = threadIdx.x;
    if ((int)blockIdx.x == nb) {
        int v = (t < G) ? g_gcnt[t] : 0;
        s[t] = v;
        __syncthreads();
        for (int o = 1; o < 1024; o <<= 1) {
            int x = (t >= o) ? s[t - o] : 0;
            __syncthreads();
            s[t] += x;
            __syncthreads();
        }
        if (t < G) {
            int ex = s[t] - g_gcnt[t];
            g_grow[t] = ex;
            g_gcur[t] = ex;
        }
        return;
    }
    int i = blockIdx.x * 1024 + t;
    int v = (i < E) ? g_cnt[i] : 0;
    s[t] = v;
    __syncthreads();
    for (int o = 1; o < 1024; o <<= 1) {
        int x = (t >= o) ? s[t - o] : 0;
        __syncthreads();
        s[t] += x;
        __syncthreads();
    }
    if (i < E) g_rowptr[i] = s[t];
    if (t == 1023) g_bsums[blockIdx.x] = s[1023];
}
__global__ void k_scan2(int nb) {
    if (threadIdx.x == 0 && blockIdx.x == 0) {
        int run = 0;
        for (int b = 0; b < nb; b++) { int t = g_bsums[b]; g_bsums[b] = run; run += t; }
    }
}
__global__ void k_scan3(int E) {
    int i = blockIdx.x * blockDim.x + threadIdx.x;
    if (i < E) {
        int ex = g_rowptr[i] - g_cnt[i] + g_bsums[i / 1024];
        g_rowptr[i] = ex;
        g_cursor[i] = ex;
    }
}
__global__ void k_fill2(const int* __restrict__ first, const int* __restrict__ second,
                        const int* __restrict__ gid, int M, int E) {
    int i = blockIdx.x * blockDim.x + threadIdx.x;
    if (i < M) {
        int pos = atomicAdd(&g_cursor[second[i]], 1);
        g_csrf[pos] = first[i];
    } else if (i < M + E) {
        int e = i - M;
        int pos = atomicAdd(&g_gcur[gid[e]], 1);
        g_glist[pos] = e;
    }
}

// ---------------- dual message aggregation (fp16 PQ, half2 lanes) -------------
__global__ void k_agg2(int E, const float* __restrict__ b_e,
                       const float* __restrict__ b_n) {
    int w = (blockIdx.x * blockDim.x + threadIdx.x) >> 5;
    if (w >= 2 * E) return;
    int side = (w >= E) ? 1 : 0;
    int e = w - side * E;
    int D = side ? 59 : 64;
    const float* bias = side ? b_n : b_e;
    const __half2* PQ2 = (const __half2*)(g_PQh[side]);

    int lane = threadIdx.x & 31;
    int c0 = lane * 2, c1 = c0 + 1;
    float2 q = __half22float2(PQ2[(size_t)e * 64 + 32 + lane]);
    float q0 = q.x + ((c0 < D) ? bias[c0] : 0.f);
    float q1 = q.y + ((c1 < D) ? bias[c1] : 0.f);
    float a0 = 0.f, a1 = 0.f;
    int s = g_rowptr[e], n = g_cnt[e];
    int i = 0;
    for (; i + 2 <= n; i += 2) {
        int f0 = g_csrf[s + i], f1 = g_csrf[s + i + 1];
        float2 p0 = __half22float2(PQ2[(size_t)f0 * 64 + lane]);
        float2 p1 = __half22float2(PQ2[(size_t)f1 * 64 + lane]);
        a0 += seluf(p0.x + q0) + seluf(p1.x + q0);
        a1 += seluf(p0.y + q1) + seluf(p1.y + q1);
    }
    for (; i < n; i++) {
        int f = g_csrf[s + i];
        float2 p = __half22float2(PQ2[(size_t)f * 64 + lane]);
        a0 += seluf(p.x + q0);
        a1 += seluf(p.y + q1);
    }
    uint32_t lo, hi = pack_f16(a0, a1, &lo);
    g_AGGhi[side][(size_t)e * 32 + lane] = hi;
    g_AGGlo[side][(size_t)e * 32 + lane] = lo;
}

// ---------------- fused dual iteration kernel ----------------------------------
#define APITCH 68
#define BPITCH 36
#define SM_AHI 0
#define SM_ALO (128 * APITCH)
#define SM_B (2 * 128 * APITCH)
#define SM_PB (2 * 128 * APITCH + 256 * APITCH)
#define SM_BIAS (SM_PB + 128 * BPITCH)
#define SM_BYTES ((SM_BIAS + 256) * 4)

__global__ void __launch_bounds__(512, 1) k_iter(
        const float* __restrict__ bxe, const float* __restrict__ bhe,
        const float* __restrict__ bxn, const float* __restrict__ bhn,
        int E, int rps, int mode, int do_pq) {
    extern __shared__ uint32_t sm[];
    float* fsm = (float*)sm;
    const int tid = threadIdx.x;
    const int wid = tid >> 5, lane = tid & 31;
    const int wrow = wid & 7, whalf = wid >> 3;
    const int gq = lane >> 2, tig = lane & 3;

    const int side = (blockIdx.x >= rps) ? 1 : 0;
    const int bid = blockIdx.x - side * rps;
    const float* bx = side ? bxn : bxe;
    const float* bh = side ? bhn : bhe;
    const int D = side ? 59 : 64;
    uint32_t* Hh = g_Hhi[side];
    uint32_t* Hl = g_Hlo[side];
    const uint32_t* Ah = g_AGGhi[side];
    const uint32_t* Al = g_AGGlo[side];
    __half* PQh = g_PQh[side];

    const int row0 = bid * 128;
    const int mrow = wrow * 16;

    const uint32_t smb = (uint32_t)__cvta_generic_to_shared(sm);
    const int arow = mrow + ((lane >> 3) & 1) * 8 + (lane & 7);
    const int acol = (lane >> 4) * 4;
    const int brow = (lane >> 4) * 8 + (lane & 7);
    const int bcol = ((lane >> 3) & 1) * 4;

    if (mode == 1) {
        // A (kp 0..31) = packed state; PB image
        for (int idx = tid; idx < 128 * 8; idx += 512) {
            int m = idx >> 3, ch = (idx & 7) * 4;
            size_t off = (size_t)(row0 + m) * 32 + ch;
            cpa16(smb + (uint32_t)(SM_AHI + m * APITCH + ch) * 4, Hh + off);
            cpa16(smb + (uint32_t)(SM_ALO + m * APITCH + ch) * 4, Hl + off);
        }
        for (int idx = tid; idx < 128 * 8; idx += 512) {
            int n = idx >> 3, ch = (idx & 7) * 4;
            cpa16(smb + (uint32_t)(SM_PB + n * BPITCH + ch) * 4,
                  g_Pw[side] + n * 32 + ch);
        }
        CP_WAIT();
        __syncthreads();
    } else {
        // A = [agg | H] packed, all via cp.async
        for (int idx = tid; idx < 128 * 8; idx += 512) {
            int m = idx >> 3, ch = (idx & 7) * 4;
            size_t off = (size_t)(row0 + m) * 32 + ch;
            cpa16(smb + (uint32_t)(SM_AHI + m * APITCH + ch) * 4, Ah + off);
            cpa16(smb + (uint32_t)(SM_ALO + m * APITCH + ch) * 4, Al + off);
            cpa16(smb + (uint32_t)(SM_AHI + m * APITCH + 32 + ch) * 4, Hh + off);
            cpa16(smb + (uint32_t)(SM_ALO + m * APITCH + 32 + ch) * 4, Hl + off);
        }
        for (int idx = tid; idx < 256 * 16; idx += 512) {
            int n = idx >> 4, ch = (idx & 15) * 4;
            cpa16(smb + (uint32_t)(SM_B + n * APITCH + ch) * 4,
                  g_Bw[side] + n * 64 + ch);
        }
        if (do_pq) {
            for (int idx = tid; idx < 128 * 8; idx += 512) {
                int n = idx >> 3, ch = (idx & 7) * 4;
                cpa16(smb + (uint32_t)(SM_PB + n * BPITCH + ch) * 4,
                      g_Pw[side] + n * 32 + ch);
            }
        }
        if (tid < 64) {
            float bz = 0.f, br = 0.f, bxh = 0.f, bhh = 0.f;
            if (tid < D) {
                bz = bx[tid] + bh[tid];
                br = bx[D + tid] + bh[D + tid];
                bxh = bx[2 * D + tid];
                bhh = bh[2 * D + tid];
            }
            fsm[SM_BIAS + tid] = bz;
            fsm[SM_BIAS + 64 + tid] = br;
            fsm[SM_BIAS + 128 + tid] = bxh;
            fsm[SM_BIAS + 192 + tid] = bhh;
        }
        CP_WAIT();
        __syncthreads();

        uint32_t stH[2][2][2], stL[2][2][2];

        for (int ci_i = 0; ci_i < 2; ci_i++) {
            int ci = whalf * 2 + ci_i;
            float acc[4][2][4] = {};

#pragma unroll
            for (int kt = 0; kt < 8; kt++) {
                uint32_t ah[4], al[4];
                ldsm4(ah, smb + (uint32_t)(SM_AHI + arow * APITCH + acol + kt * 8) * 4);
                ldsm4(al, smb + (uint32_t)(SM_ALO + arow * APITCH + acol + kt * 8) * 4);
#pragma unroll
                for (int g4 = 0; g4 < 4; g4++) {
                    uint32_t b[4];
                    ldsm4(b, smb + (uint32_t)(SM_B + (g4 * 64 + ci * 16 + brow) * APITCH +
                                              bcol + kt * 8) * 4);
                    mma16816(acc[g4][0], ah[0], ah[1], ah[2], ah[3], b[0], b[1]);
                    mma16816(acc[g4][0], al[0], al[1], al[2], al[3], b[0], b[1]);
                    mma16816(acc[g4][1], ah[0], ah[1], ah[2], ah[3], b[2], b[3]);
                    mma16816(acc[g4][1], al[0], al[1], al[2], al[3], b[2], b[3]);
                }
            }

            // GRU epilogue: h_old from staged smem (hi+lo), fast transcendentals
#pragma unroll
            for (int nt = 0; nt < 2; nt++) {
#pragma unroll
                for (int rh = 0; rh < 2; rh++) {
                    int m = mrow + gq + rh * 8;
                    int r = row0 + m;
                    int c0 = ci * 16 + nt * 8 + tig * 2;
                    int widx = c0 >> 1;
                    uint32_t hw = sm[SM_AHI + m * APITCH + 32 + widx];
                    uint32_t lw = sm[SM_ALO + m * APITCH + 32 + widx];

                    float hold0 = f16lo(hw) + f16lo(lw);
                    float z0 = sigm(acc[0][nt][rh * 2] + fsm[SM_BIAS + c0]);
                    float rr0 = sigm(acc[1][nt][rh * 2] + fsm[SM_BIAS + 64 + c0]);
                    float cand0 = tanha(acc[2][nt][rh * 2] + fsm[SM_BIAS + 128 + c0] +
                                        rr0 * (acc[3][nt][rh * 2] + fsm[SM_BIAS + 192 + c0]));
                    float h0 = z0 * hold0 + (1.f - z0) * cand0;

                    int c1 = c0 + 1;
                    float hold1 = f16hi(hw) + f16hi(lw);
                    float z1 = sigm(acc[0][nt][rh * 2 + 1] + fsm[SM_BIAS + c1]);
                    float rr1 = sigm(acc[1][nt][rh * 2 + 1] + fsm[SM_BIAS + 64 + c1]);
                    float cand1 = tanha(acc[2][nt][rh * 2 + 1] + fsm[SM_BIAS + 128 + c1] +
                                        rr1 * (acc[3][nt][rh * 2 + 1] + fsm[SM_BIAS + 192 + c1]));
                    float h1 = z1 * hold1 + (1.f - z1) * cand1;

                    uint32_t lo, hi = pack_f16(h0, h1, &lo);
                    size_t gw = (size_t)r * 32 + widx;
                    Hh[gw] = hi;
                    Hl[gw] = lo;
                    stH[ci_i][nt][rh] = hi;
                    stL[ci_i][nt][rh] = lo;
                }
            }
        }

        if (!do_pq) return;
        __syncthreads();   // all warps done reading A/B for GRU

        // stash Hnew into A region (kp < 32)
#pragma unroll
        for (int ci_i = 0; ci_i < 2; ci_i++) {
            int ci = whalf * 2 + ci_i;
#pragma unroll
            for (int nt = 0; nt < 2; nt++) {
#pragma unroll
                for (int rh = 0; rh < 2; rh++) {
                    int kp = ci * 8 + nt * 4 + tig;
                    int m = mrow + gq + rh * 8;
                    sm[SM_AHI + m * APITCH + kp] = stH[ci_i][nt][rh];
                    sm[SM_ALO + m * APITCH + kp] = stL[ci_i][nt][rh];
                }
            }
        }
        __syncthreads();
    }

    // ---- PQ mma: PQ[128 x 128] = A(kp<32) @ Bpq^T ----
    float acc2[8][4] = {};
#pragma unroll
    for (int kt = 0; kt < 4; kt++) {
        uint32_t ah[4], al[4];
        ldsm4(ah, smb + (uint32_t)(SM_AHI + arow * APITCH + acol + kt * 8) * 4);
        ldsm4(al, smb + (uint32_t)(SM_ALO + arow * APITCH + acol + kt * 8) * 4);
#pragma unroll
        for (int np = 0; np < 4; np++) {
            uint32_t b[4];
            ldsm4(b, smb + (uint32_t)(SM_PB + (whalf * 64 + np * 16 + brow) * BPITCH +
                                      bcol + kt * 8) * 4);
            mma16816(acc2[np * 2], ah[0], ah[1], ah[2], ah[3], b[0], b[1]);
            mma16816(acc2[np * 2], al[0], al[1], al[2], al[3], b[0], b[1]);
            mma16816(acc2[np * 2 + 1], ah[0], ah[1], ah[2], ah[3], b[2], b[3]);
            mma16816(acc2[np * 2 + 1], al[0], al[1], al[2], al[3], b[2], b[3]);
        }
    }

    int r0 = row0 + mrow + gq, r1 = r0 + 8;
#pragma unroll
    for (int nt2 = 0; nt2 < 8; nt2++) {
        int cb = whalf * 64 + nt2 * 8 + tig * 2;
        *(__half2*)&PQh[(size_t)r0 * 128 + cb] = __floats2half2_rn(acc2[nt2][0], acc2[nt2][1]);
        *(__half2*)&PQh[(size_t)r1 * 128 + cb] = __floats2half2_rn(acc2[nt2][2], acc2[nt2][3]);
    }
}

// ---------------- readout -----------------------------------------------------
__global__ void k_pool2(int G) {
    int g = blockIdx.x;
    int c = threadIdx.x;
    if (c >= 123) return;
    int side = (c < 64) ? 0 : 1;
    int cc = (c < 64) ? c : c - 64;
    int widx = cc >> 1, hiHalf = cc & 1;
    int s = g_grow[g], n = g_gcnt[g];
    float acc = 0.f;
    for (int j = 0; j < n; j++) {
        int e = g_glist[s + j];
        uint32_t hw = g_Hhi[side][(size_t)e * 32 + widx];
        uint32_t lw = g_Hlo[side][(size_t)e * 32 + widx];
        acc += hiHalf ? (f16hi(hw) + f16hi(lw)) : (f16lo(hw) + f16lo(lw));
    }
    g_pool[g * 123 + c] = acc;
}
__global__ void k_mlp(const float* __restrict__ in, int ldin, int K,
                      const float* __restrict__ W, const float* __restrict__ b,
                      int N, float* __restrict__ out, int ldout, int act) {
    __shared__ float s[256];
    int row = blockIdx.x;
    for (int k = threadIdx.x; k < K; k += blockDim.x) s[k] = in[row * ldin + k];
    __syncthreads();
    for (int t = threadIdx.x; t < N; t += blockDim.x) {
        float acc = b[t];
        for (int k = 0; k < K; k++) acc += s[k] * W[k * N + t];
        if (act) acc = seluf(acc);
        out[row * ldout + t] = acc;
    }
}

// ---------------- launch ------------------------------------------------------
extern "C" void kernel_launch(void* const* d_in, const int* in_sizes, int n_in,
                              void* d_out, int out_size) {
    int idx = 0;
    const float* graph_state = (const float*)d_in[idx++];
    const float* node_state  = (const float*)d_in[idx++];
    const int*   first       = (const int*)d_in[idx++];
    const int*   second      = (const int*)d_in[idx++];
    const int*   gids        = (const int*)d_in[idx++];
    if (idx < n_in && in_sizes[idx] == 1) idx++;   // scalar states_num_edges
    const float* W_msg  = (const float*)d_in[idx++];
    const float* b_msg  = (const float*)d_in[idx++];
    const float* Wx_e   = (const float*)d_in[idx++];
    const float* Wh_e   = (const float*)d_in[idx++];
    const float* bx_e   = (const float*)d_in[idx++];
    const float* bh_e   = (const float*)d_in[idx++];
    const float* W_nmsg = (const float*)d_in[idx++];
    const float* b_nmsg = (const float*)d_in[idx++];
    const float* Wx_n   = (const float*)d_in[idx++];
    const float* Wh_n   = (const float*)d_in[idx++];
    const float* bx_n   = (const float*)d_in[idx++];
    const float* bh_n   = (const float*)d_in[idx++];
    const float* W1     = (const float*)d_in[idx++];
    const float* b1     = (const float*)d_in[idx++];
    const float* W2     = (const float*)d_in[idx++];
    const float* b2     = (const float*)d_in[idx++];
    const float* W3     = (const float*)d_in[idx++];
    const float* b3     = (const float*)d_in[idx++];

    const int E = in_sizes[0] / 64;
    const int M = in_sizes[3];
    const int G = out_size;

    float *POOL, *H1, *H2;
    cudaGetSymbolAddress((void**)&POOL, g_pool);
    cudaGetSymbolAddress((void**)&H1, g_h1);
    cudaGetSymbolAddress((void**)&H2, g_h2);

    cudaFuncSetAttribute(k_iter, cudaFuncAttributeMaxDynamicSharedMemorySize,
                         SM_BYTES);

    const int T256 = 256;
    auto gs = [](int n, int b) { return (n + b - 1) / b; };
    const int rps = gs(E, 128);
    const int nb = gs(E, 1024);

    // L1: fused setup (state packing + weight images + zeroing)
    int total = E * 64 + 2 * 256 * 128 + 2 * 128 * 64 + E + G;
    k_setup<<<gs(total, T256), T256>>>(graph_state, node_state, Wx_e, Wh_e,
                                       Wx_n, Wh_n, W_msg, W_nmsg, E, G);
    // L2: histograms
    k_hist2<<<gs(M + E, T256), T256>>>(second, gids, M, E);
    // L3: block scans (edge CSR) + graph scan
    k_scan1g<<<nb + 1, 1024>>>(E, G, nb);
    // L4: initial PQ projection (positioned 4th for ncu capture)
    k_iter<<<2 * rps, 512, SM_BYTES>>>(bx_e, bh_e, bx_n, bh_n, E, rps, 1, 1);
    // L5-L7: finish CSR build
    k_scan2<<<1, 32>>>(nb);
    k_scan3<<<gs(E, T256), T256>>>(E);
    k_fill2<<<gs(M + E, T256), T256>>>(first, second, gids, M, E);

    // ---- dual message passing: T=4, edge+node in the same launches ----
    for (int t = 0; t < 4; t++) {
        k_agg2<<<gs(2 * E * 32, 256), 256>>>(E, b_msg, b_nmsg);
        k_iter<<<2 * rps, 512, SM_BYTES>>>(bx_e, bh_e, bx_n, bh_n, E, rps, 0, t < 3);
    }

    // ---- readout ----
    k_pool2<<<G, 128>>>(G);
    k_mlp<<<G, 256>>>(POOL, 123, 123, W1, b1, 256, H1, 256, 1);
    k_mlp<<<G, 256>>>(H1, 256, 256, W2, b2, 256, H2, 256, 1);
    k_mlp<<<G, 256>>>(H2, 256, 256, W3, b3, 1, (float*)d_out, 1, 0);
}